// round 1
// baseline (speedup 1.0000x reference)
#include <cuda_runtime.h>
#include <cuda_bf16.h>

// ---------------------------------------------------------------------------
// Problem constants (fixed shapes from setup_inputs)
// ---------------------------------------------------------------------------
#define B      16
#define N1     4096
#define N2     1024
#define C1     128
#define C2     256
#define CIN    (C1 + C2)     // 384
#define M0     256           // mlp[0]
#define M1     128           // mlp[1]
#define NTOT   (B * N1)      // 65536 columns
#define BN_EPS 1e-5f

// ---------------------------------------------------------------------------
// Scratch (device globals; no runtime allocation allowed)
// ---------------------------------------------------------------------------
__device__ float g_interp[(size_t)C2 * NTOT];    // 64 MB  (c2, j)
__device__ float g_y0[(size_t)M0 * NTOT];        // 64 MB  (m0, j)
__device__ float g_y1[(size_t)M1 * NTOT];        // 32 MB  (m1, j)
__device__ int   g_idx3[NTOT * 3];
__device__ float g_w3[NTOT * 3];
__device__ float g_s0[M0], g_q0[M0], g_scale0[M0], g_shift0[M0];
__device__ float g_s1[M1], g_q1[M1], g_scale1[M1], g_shift1[M1];

// ---------------------------------------------------------------------------
// Kernel 1: 3-NN (one thread per query point, xyz2 tile in SMEM)
// grid (N1/256, B), block 256
// ---------------------------------------------------------------------------
__global__ __launch_bounds__(256) void knn_kernel(const float* __restrict__ xyz1,
                                                  const float* __restrict__ xyz2)
{
    __shared__ float4 s2[N2];
    const int b = blockIdx.y;
    const float* x2 = xyz2 + (size_t)b * N2 * 3;
    for (int i = threadIdx.x; i < N2; i += blockDim.x) {
        s2[i] = make_float4(x2[i * 3 + 0], x2[i * 3 + 1], x2[i * 3 + 2], 0.0f);
    }
    __syncthreads();

    const int n = blockIdx.x * blockDim.x + threadIdx.x;
    const float* p = xyz1 + ((size_t)b * N1 + n) * 3;
    const float px = p[0], py = p[1], pz = p[2];

    float d0 = 1e30f, d1 = 1e30f, d2 = 1e30f;
    int   i0 = 0,     i1 = 0,     i2 = 0;

    #pragma unroll 4
    for (int i = 0; i < N2; i++) {
        float4 q = s2[i];
        float dx = px - q.x, dy = py - q.y, dz = pz - q.z;
        float d = dx * dx;
        d = fmaf(dy, dy, d);
        d = fmaf(dz, dz, d);
        if (d < d2) {
            if (d < d1) {
                d2 = d1; i2 = i1;
                if (d < d0) { d1 = d0; i1 = i0; d0 = d; i0 = i; }
                else        { d1 = d;  i1 = i; }
            } else { d2 = d; i2 = i; }
        }
    }

    float w0_ = 1.0f / (d0 + 1e-8f);
    float w1_ = 1.0f / (d1 + 1e-8f);
    float w2_ = 1.0f / (d2 + 1e-8f);
    float inv = 1.0f / (w0_ + w1_ + w2_);

    const int base = ((size_t)b * N1 + n) * 3;
    g_idx3[base + 0] = i0; g_idx3[base + 1] = i1; g_idx3[base + 2] = i2;
    g_w3[base + 0] = w0_ * inv;
    g_w3[base + 1] = w1_ * inv;
    g_w3[base + 2] = w2_ * inv;
}

// ---------------------------------------------------------------------------
// Kernel 2: interpolation -> g_interp[(c, j)], j = b*N1 + n
// grid NTOT/128, block 128; each thread owns one column j, loops channels
// ---------------------------------------------------------------------------
__global__ __launch_bounds__(128) void interp_kernel(const float* __restrict__ feat2)
{
    const int j = blockIdx.x * 128 + threadIdx.x;
    const int b = j >> 12;               // j / 4096
    const int base = j * 3;
    const int i0 = g_idx3[base + 0];
    const int i1 = g_idx3[base + 1];
    const int i2 = g_idx3[base + 2];
    const float w0_ = g_w3[base + 0];
    const float w1_ = g_w3[base + 1];
    const float w2_ = g_w3[base + 2];

    const float* f2 = feat2 + (size_t)b * C2 * N2;
    #pragma unroll 4
    for (int c = 0; c < C2; c++) {
        const float* row = f2 + (size_t)c * N2;
        float v = __ldg(row + i0) * w0_;
        v = fmaf(__ldg(row + i1), w1_, v);
        v = fmaf(__ldg(row + i2), w2_, v);
        g_interp[(size_t)c * NTOT + j] = v;
    }
}

// ---------------------------------------------------------------------------
// SGEMM tiles: 128x128 block tile, BK=16, 256 threads, 8x8 per thread
// ---------------------------------------------------------------------------
#define BM 128
#define BNt 128
#define BK 16
#define TM 8
#define TN 8

// GEMM1: y0 = w0(256x384) @ X(384x65536) + b0, where X rows [0,128) = feat1,
// rows [128,384) = g_interp. Column tiles never cross a batch (4096 % 128 == 0).
__global__ __launch_bounds__(256) void gemm1_kernel(const float* __restrict__ w0,
                                                    const float* __restrict__ feat1,
                                                    const float* __restrict__ b0)
{
    __shared__ float As[BK][BM];
    __shared__ float Bs[BK][BNt];

    const int tid = threadIdx.x;
    const int m0 = blockIdx.y * BM;
    const int j0 = blockIdx.x * BNt;
    const int b  = j0 >> 12;
    const int n0 = j0 & (N1 - 1);
    const float* f1 = feat1 + (size_t)b * C1 * N1 + n0;

    const int tx = tid & 15, ty = tid >> 4;
    const int arow = tid >> 2;          // 0..63
    const int acol = (tid & 3) * 4;     // 0,4,8,12
    const int brow = tid >> 5;          // 0..7
    const int bcol = (tid & 31) * 4;    // 0..124

    float acc[TM][TN] = {};

    for (int k0 = 0; k0 < CIN; k0 += BK) {
        #pragma unroll
        for (int r = 0; r < 2; r++) {
            int m = arow + r * 64;
            float4 v = *(const float4*)(w0 + (size_t)(m0 + m) * CIN + k0 + acol);
            As[acol + 0][m] = v.x; As[acol + 1][m] = v.y;
            As[acol + 2][m] = v.z; As[acol + 3][m] = v.w;
        }
        #pragma unroll
        for (int r = 0; r < 2; r++) {
            int k = brow + r * 8;
            int kk = k0 + k;
            float4 v;
            if (kk < C1) v = *(const float4*)(f1 + (size_t)kk * N1 + bcol);
            else         v = *(const float4*)(g_interp + (size_t)(kk - C1) * NTOT + j0 + bcol);
            *(float4*)&Bs[k][bcol] = v;
        }
        __syncthreads();
        #pragma unroll
        for (int k = 0; k < BK; k++) {
            float a[TM], bb[TN];
            #pragma unroll
            for (int i = 0; i < TM; i++) a[i] = As[k][ty * TM + i];
            #pragma unroll
            for (int i = 0; i < TN; i++) bb[i] = Bs[k][tx * TN + i];
            #pragma unroll
            for (int i = 0; i < TM; i++)
                #pragma unroll
                for (int jj = 0; jj < TN; jj++)
                    acc[i][jj] = fmaf(a[i], bb[jj], acc[i][jj]);
        }
        __syncthreads();
    }

    #pragma unroll
    for (int i = 0; i < TM; i++) {
        int m = m0 + ty * TM + i;
        float bias = __ldg(b0 + m);
        float* dst = g_y0 + (size_t)m * NTOT + j0 + tx * TN;
        #pragma unroll
        for (int jj = 0; jj < TN; jj += 4) {
            float4 v;
            v.x = acc[i][jj + 0] + bias; v.y = acc[i][jj + 1] + bias;
            v.z = acc[i][jj + 2] + bias; v.w = acc[i][jj + 3] + bias;
            *(float4*)(dst + jj) = v;
        }
    }
}

// GEMM2: y1 = w1(128x256) @ relu(bn1(y0)) + b1; BN1+ReLU fused into B-tile load
__global__ __launch_bounds__(256) void gemm2_kernel(const float* __restrict__ w1,
                                                    const float* __restrict__ b1)
{
    __shared__ float As[BK][BM];
    __shared__ float Bs[BK][BNt];
    __shared__ float s_scale[M0];
    __shared__ float s_shift[M0];

    const int tid = threadIdx.x;
    s_scale[tid] = g_scale0[tid];
    s_shift[tid] = g_shift0[tid];
    __syncthreads();

    const int j0 = blockIdx.x * BNt;
    const int tx = tid & 15, ty = tid >> 4;
    const int arow = tid >> 2;
    const int acol = (tid & 3) * 4;
    const int brow = tid >> 5;
    const int bcol = (tid & 31) * 4;

    float acc[TM][TN] = {};

    for (int k0 = 0; k0 < M0; k0 += BK) {
        #pragma unroll
        for (int r = 0; r < 2; r++) {
            int m = arow + r * 64;
            float4 v = *(const float4*)(w1 + (size_t)m * M0 + k0 + acol);
            As[acol + 0][m] = v.x; As[acol + 1][m] = v.y;
            As[acol + 2][m] = v.z; As[acol + 3][m] = v.w;
        }
        #pragma unroll
        for (int r = 0; r < 2; r++) {
            int k = brow + r * 8;
            int kk = k0 + k;
            float4 v = *(const float4*)(g_y0 + (size_t)kk * NTOT + j0 + bcol);
            float sc = s_scale[kk], sh = s_shift[kk];
            v.x = fmaxf(fmaf(v.x, sc, sh), 0.0f);
            v.y = fmaxf(fmaf(v.y, sc, sh), 0.0f);
            v.z = fmaxf(fmaf(v.z, sc, sh), 0.0f);
            v.w = fmaxf(fmaf(v.w, sc, sh), 0.0f);
            *(float4*)&Bs[k][bcol] = v;
        }
        __syncthreads();
        #pragma unroll
        for (int k = 0; k < BK; k++) {
            float a[TM], bb[TN];
            #pragma unroll
            for (int i = 0; i < TM; i++) a[i] = As[k][ty * TM + i];
            #pragma unroll
            for (int i = 0; i < TN; i++) bb[i] = Bs[k][tx * TN + i];
            #pragma unroll
            for (int i = 0; i < TM; i++)
                #pragma unroll
                for (int jj = 0; jj < TN; jj++)
                    acc[i][jj] = fmaf(a[i], bb[jj], acc[i][jj]);
        }
        __syncthreads();
    }

    #pragma unroll
    for (int i = 0; i < TM; i++) {
        int m = ty * TM + i;
        float bias = __ldg(b1 + m);
        float* dst = g_y1 + (size_t)m * NTOT + j0 + tx * TN;
        #pragma unroll
        for (int jj = 0; jj < TN; jj += 4) {
            float4 v;
            v.x = acc[i][jj + 0] + bias; v.y = acc[i][jj + 1] + bias;
            v.z = acc[i][jj + 2] + bias; v.w = acc[i][jj + 3] + bias;
            *(float4*)(dst + jj) = v;
        }
    }
}

// ---------------------------------------------------------------------------
// Per-channel stats: one block per channel, 256 threads reduce 65536 values
// ---------------------------------------------------------------------------
template <bool FIRST>
__global__ __launch_bounds__(256) void stats_kernel()
{
    const float* y = FIRST ? g_y0 : g_y1;
    float* s_out = FIRST ? g_s0 : g_s1;
    float* q_out = FIRST ? g_q0 : g_q1;

    const int c = blockIdx.x;
    const float* row = y + (size_t)c * NTOT;
    float s = 0.0f, q = 0.0f;
    for (int i = threadIdx.x; i < NTOT; i += 256) {
        float v = row[i];
        s += v;
        q = fmaf(v, v, q);
    }
    __shared__ float sh_s[256], sh_q[256];
    sh_s[threadIdx.x] = s;
    sh_q[threadIdx.x] = q;
    __syncthreads();
    for (int off = 128; off > 0; off >>= 1) {
        if (threadIdx.x < off) {
            sh_s[threadIdx.x] += sh_s[threadIdx.x + off];
            sh_q[threadIdx.x] += sh_q[threadIdx.x + off];
        }
        __syncthreads();
    }
    if (threadIdx.x == 0) {
        s_out[c] = sh_s[0];
        q_out[c] = sh_q[0];
    }
}

template <bool FIRST>
__global__ void finalize_kernel(const float* __restrict__ g,
                                const float* __restrict__ be, int C)
{
    int c = blockIdx.x * blockDim.x + threadIdx.x;
    if (c < C) {
        const float* s = FIRST ? g_s0 : g_s1;
        const float* q = FIRST ? g_q0 : g_q1;
        float* scale = FIRST ? g_scale0 : g_scale1;
        float* shift = FIRST ? g_shift0 : g_shift1;
        float mean = s[c] * (1.0f / NTOT);
        float var  = q[c] * (1.0f / NTOT) - mean * mean;
        float sc = g[c] * rsqrtf(var + BN_EPS);
        scale[c] = sc;
        shift[c] = be[c] - mean * sc;
    }
}

// ---------------------------------------------------------------------------
// Final elementwise BN2 + ReLU -> d_out, layout (b, c, n)
// ---------------------------------------------------------------------------
__global__ __launch_bounds__(256) void bnrelu_out_kernel(float* __restrict__ out)
{
    int o = blockIdx.x * 256 + threadIdx.x;        // 0 .. 8388607
    int n = o & (N1 - 1);
    int c = (o >> 12) & (M1 - 1);
    int b = o >> 19;
    float v = g_y1[(size_t)c * NTOT + b * N1 + n];
    out[o] = fmaxf(fmaf(v, g_scale1[c], g_shift1[c]), 0.0f);
}

// ---------------------------------------------------------------------------
// Launch
// ---------------------------------------------------------------------------
extern "C" void kernel_launch(void* const* d_in, const int* in_sizes, int n_in,
                              void* d_out, int out_size)
{
    const float* xyz1  = (const float*)d_in[0];
    const float* xyz2  = (const float*)d_in[1];
    const float* feat1 = (const float*)d_in[2];
    const float* feat2 = (const float*)d_in[3];
    const float* w0    = (const float*)d_in[4];
    const float* b0    = (const float*)d_in[5];
    const float* g0    = (const float*)d_in[6];
    const float* be0   = (const float*)d_in[7];
    const float* w1    = (const float*)d_in[8];
    const float* b1    = (const float*)d_in[9];
    const float* g1    = (const float*)d_in[10];
    const float* be1   = (const float*)d_in[11];
    float* out = (float*)d_out;

    knn_kernel<<<dim3(N1 / 256, B), 256>>>(xyz1, xyz2);
    interp_kernel<<<NTOT / 128, 128>>>(feat2);
    gemm1_kernel<<<dim3(NTOT / BNt, M0 / BM), 256>>>(w0, feat1, b0);
    stats_kernel<true><<<M0, 256>>>();
    finalize_kernel<true><<<1, M0>>>(g0, be0, M0);
    gemm2_kernel<<<NTOT / BNt, 256>>>(w1, b1);
    stats_kernel<false><<<M1, 256>>>();
    finalize_kernel<false><<<1, M1>>>(g1, be1, M1);
    bnrelu_out_kernel<<<(B * M1 * N1) / 256, 256>>>(out);
}

// round 3
// speedup vs baseline: 1.4320x; 1.4320x over previous
#include <cuda_runtime.h>
#include <cstdint>

// ---------------------------------------------------------------------------
// Problem constants
// ---------------------------------------------------------------------------
constexpr int NB   = 16;
constexpr int N1v  = 4096;
constexpr int N2v  = 1024;
constexpr int C1v  = 128;
constexpr int C2v  = 256;
constexpr int CINv = 384;
constexpr int M0v  = 256;
constexpr int M1v  = 128;
constexpr int NTOTv = NB * N1v;   // 65536
#define BN_EPS 1e-5f

// ---------------------------------------------------------------------------
// Scratch (device globals)
// ---------------------------------------------------------------------------
__device__ float g_interp[(size_t)C2v * NTOTv];   // 64 MB
__device__ float g_y0[(size_t)M0v * NTOTv];       // 64 MB
__device__ float g_y1[(size_t)M1v * NTOTv];       // 32 MB
__device__ int   g_idx3[NTOTv * 3];
__device__ float g_w3[NTOTv * 3];
__device__ float g_s0[M0v], g_q0[M0v], g_scale0[M0v], g_shift0[M0v];
__device__ float g_s1[M1v], g_q1[M1v], g_scale1[M1v], g_shift1[M1v];

// ---------------------------------------------------------------------------
// Helpers
// ---------------------------------------------------------------------------
__device__ __forceinline__ float tf32r(float x) {
    uint32_t u;
    asm("cvt.rna.tf32.f32 %0, %1;" : "=r"(u) : "f"(x));
    return __uint_as_float(u);
}

__device__ __forceinline__ void mma8(float& d0, float& d1, float& d2, float& d3,
                                     uint32_t a0, uint32_t a1, uint32_t a2, uint32_t a3,
                                     uint32_t b0, uint32_t b1) {
    asm volatile(
        "mma.sync.aligned.m16n8k8.row.col.f32.tf32.tf32.f32 "
        "{%0,%1,%2,%3}, {%4,%5,%6,%7}, {%8,%9}, {%0,%1,%2,%3};"
        : "+f"(d0), "+f"(d1), "+f"(d2), "+f"(d3)
        : "r"(a0), "r"(a1), "r"(a2), "r"(a3), "r"(b0), "r"(b1));
}

// ---------------------------------------------------------------------------
// Kernel: 3-NN
// ---------------------------------------------------------------------------
__global__ __launch_bounds__(256) void knn_kernel(const float* __restrict__ xyz1,
                                                  const float* __restrict__ xyz2)
{
    __shared__ float4 s2[N2v];
    const int b = blockIdx.y;
    const float* x2 = xyz2 + (size_t)b * N2v * 3;
    for (int i = threadIdx.x; i < N2v; i += blockDim.x)
        s2[i] = make_float4(x2[i * 3 + 0], x2[i * 3 + 1], x2[i * 3 + 2], 0.0f);
    __syncthreads();

    const int n = blockIdx.x * blockDim.x + threadIdx.x;
    const float* p = xyz1 + ((size_t)b * N1v + n) * 3;
    const float px = p[0], py = p[1], pz = p[2];

    float d0 = 1e30f, d1 = 1e30f, d2 = 1e30f;
    int   i0 = 0,     i1 = 0,     i2 = 0;

    #pragma unroll 4
    for (int i = 0; i < N2v; i++) {
        float4 q = s2[i];
        float dx = px - q.x, dy = py - q.y, dz = pz - q.z;
        float d = dx * dx;
        d = fmaf(dy, dy, d);
        d = fmaf(dz, dz, d);
        if (d < d2) {
            if (d < d1) {
                d2 = d1; i2 = i1;
                if (d < d0) { d1 = d0; i1 = i0; d0 = d; i0 = i; }
                else        { d1 = d;  i1 = i; }
            } else { d2 = d; i2 = i; }
        }
    }

    float w0_ = 1.0f / (d0 + 1e-8f);
    float w1_ = 1.0f / (d1 + 1e-8f);
    float w2_ = 1.0f / (d2 + 1e-8f);
    float inv = 1.0f / (w0_ + w1_ + w2_);

    const int base = ((size_t)b * N1v + n) * 3;
    g_idx3[base + 0] = i0; g_idx3[base + 1] = i1; g_idx3[base + 2] = i2;
    g_w3[base + 0] = w0_ * inv;
    g_w3[base + 1] = w1_ * inv;
    g_w3[base + 2] = w2_ * inv;
}

// ---------------------------------------------------------------------------
// Kernel: SMEM-tiled interpolation (feat2 channel group resident in SMEM)
// ---------------------------------------------------------------------------
__global__ __launch_bounds__(256) void interp_tiled(const float* __restrict__ feat2)
{
    extern __shared__ float tile[];  // [32][1024]
    const int b  = blockIdx.x >> 3;
    const int cg = blockIdx.x & 7;
    const float* src = feat2 + ((size_t)b * C2v + cg * 32) * N2v;
    for (int x = threadIdx.x; x < 32 * N2v; x += 256)
        tile[x] = src[x];
    __syncthreads();

    for (int j = threadIdx.x; j < N1v; j += 256) {
        const int jg = b * N1v + j;
        const int i0 = g_idx3[jg * 3 + 0];
        const int i1 = g_idx3[jg * 3 + 1];
        const int i2 = g_idx3[jg * 3 + 2];
        const float w0_ = g_w3[jg * 3 + 0];
        const float w1_ = g_w3[jg * 3 + 1];
        const float w2_ = g_w3[jg * 3 + 2];
        #pragma unroll 8
        for (int c = 0; c < 32; c++) {
            const float* row = tile + c * N2v;
            float v = row[i0] * w0_;
            v = fmaf(row[i1], w1_, v);
            v = fmaf(row[i2], w2_, v);
            g_interp[(size_t)(cg * 32 + c) * NTOTv + jg] = v;
        }
    }
}

// ---------------------------------------------------------------------------
// GEMM via mma.sync tf32 (3-term split), fused bias + BN-stat atomics.
//   MODE 0: B = concat(feat1, g_interp); out = g_y0, stats -> s0/q0
//   MODE 1: B = relu(bn1(g_y0));         out = g_y1, stats -> s1/q1
// Grid: (M/128, NTOT/128); block 256 (8 warps, 2m x 4n of 64x32).
// SMEM layout per stage (floats): Ahi[128][36] | Alo | Bhi[32][136] | Blo
// ---------------------------------------------------------------------------
constexpr int SA = 36;                  // A smem row stride (floats)
constexpr int SB = 136;                 // B smem row stride (floats)
constexpr int OFF_ALO = 128 * SA;       // 4608
constexpr int OFF_BHI = 2 * 128 * SA;   // 9216
constexpr int OFF_BLO = OFF_BHI + 32 * SB;  // 13568
constexpr int STAGE_F = OFF_BHI + 2 * 32 * SB;  // 17920 floats = 71680 B

template <int KTOT, int MODE>
__global__ __launch_bounds__(256, 1) void gemm_mma(const float* __restrict__ Aw,
                                                   const float* __restrict__ feat1,
                                                   const float* __restrict__ bias)
{
    constexpr int NC = KTOT / 32;
    extern __shared__ float sm[];

    const int tid  = threadIdx.x;
    const int lane = tid & 31;
    const int wid  = tid >> 5;
    const int wm   = wid >> 2;          // 0..1
    const int wn   = wid & 3;           // 0..3
    const int m0g  = blockIdx.x * 128;
    const int j0   = blockIdx.y * 128;
    const int b    = j0 >> 12;
    const int n0l  = j0 & (N1v - 1);

    float acc[4][4][4] = {};
    float4 aR[4], bR[4];

    // ---- stage loaders -----------------------------------------------------
    auto ldgA = [&](int i) {
        const int k0 = i * 32;
        #pragma unroll
        for (int r = 0; r < 4; r++) {
            const int e  = r * 256 + tid;
            const int m  = e >> 3;
            const int k4 = e & 7;
            aR[r] = *(const float4*)(Aw + (size_t)(m0g + m) * KTOT + k0 + k4 * 4);
        }
    };
    auto ldgB = [&](int i) {
        const int k0 = i * 32;
        #pragma unroll
        for (int r = 0; r < 4; r++) {
            const int e    = r * 256 + tid;
            const int krow = e >> 5;
            const int j4   = e & 31;
            const int kg   = k0 + krow;
            const float* src;
            if (MODE == 0) {
                src = (kg < C1v)
                    ? (feat1 + ((size_t)b * C1v + kg) * N1v + n0l)
                    : (g_interp + (size_t)(kg - C1v) * NTOTv + j0);
            } else {
                src = g_y0 + (size_t)kg * NTOTv + j0;
            }
            float4 v = *(const float4*)(src + j4 * 4);
            if (MODE == 1) {
                const float sc = g_scale0[kg], sh = g_shift0[kg];
                v.x = fmaxf(fmaf(v.x, sc, sh), 0.0f);
                v.y = fmaxf(fmaf(v.y, sc, sh), 0.0f);
                v.z = fmaxf(fmaf(v.z, sc, sh), 0.0f);
                v.w = fmaxf(fmaf(v.w, sc, sh), 0.0f);
            }
            bR[r] = v;
        }
    };
    auto sts = [&](int s) {
        float* S = sm + s * STAGE_F;
        #pragma unroll
        for (int r = 0; r < 4; r++) {
            const int e  = r * 256 + tid;
            const int m  = e >> 3;
            const int k4 = e & 7;
            float4 v = aR[r];
            float4 h = make_float4(tf32r(v.x), tf32r(v.y), tf32r(v.z), tf32r(v.w));
            float4 l = make_float4(tf32r(v.x - h.x), tf32r(v.y - h.y),
                                   tf32r(v.z - h.z), tf32r(v.w - h.w));
            const int o = m * SA + k4 * 4;
            *(float4*)(S + o)           = h;
            *(float4*)(S + OFF_ALO + o) = l;
        }
        #pragma unroll
        for (int r = 0; r < 4; r++) {
            const int e    = r * 256 + tid;
            const int krow = e >> 5;
            const int j4   = e & 31;
            float4 v = bR[r];
            float4 h = make_float4(tf32r(v.x), tf32r(v.y), tf32r(v.z), tf32r(v.w));
            float4 l = make_float4(tf32r(v.x - h.x), tf32r(v.y - h.y),
                                   tf32r(v.z - h.z), tf32r(v.w - h.w));
            const int o = krow * SB + j4 * 4;
            *(float4*)(S + OFF_BHI + o) = h;
            *(float4*)(S + OFF_BLO + o) = l;
        }
    };

    // ---- fragment compute ---------------------------------------------------
    const int abase = (wm * 64 + (lane >> 2)) * SA + (lane & 3);
    const int bbase = (lane & 3) * SB + wn * 32 + (lane >> 2);

    auto compute = [&](int s) {
        const float* S = sm + s * STAGE_F;
        #pragma unroll
        for (int ks = 0; ks < 4; ks++) {
            uint32_t ah[4][4], al[4][4];
            #pragma unroll
            for (int mi = 0; mi < 4; mi++) {
                const int ia = abase + mi * 16 * SA + ks * 8;
                ah[mi][0] = __float_as_uint(S[ia]);
                ah[mi][1] = __float_as_uint(S[ia + 8 * SA]);
                ah[mi][2] = __float_as_uint(S[ia + 4]);
                ah[mi][3] = __float_as_uint(S[ia + 8 * SA + 4]);
                al[mi][0] = __float_as_uint(S[OFF_ALO + ia]);
                al[mi][1] = __float_as_uint(S[OFF_ALO + ia + 8 * SA]);
                al[mi][2] = __float_as_uint(S[OFF_ALO + ia + 4]);
                al[mi][3] = __float_as_uint(S[OFF_ALO + ia + 8 * SA + 4]);
            }
            #pragma unroll
            for (int ni = 0; ni < 4; ni++) {
                const int ib = bbase + ks * 8 * SB + ni * 8;
                const uint32_t bh0 = __float_as_uint(S[OFF_BHI + ib]);
                const uint32_t bh1 = __float_as_uint(S[OFF_BHI + ib + 4 * SB]);
                const uint32_t bl0 = __float_as_uint(S[OFF_BLO + ib]);
                const uint32_t bl1 = __float_as_uint(S[OFF_BLO + ib + 4 * SB]);
                #pragma unroll
                for (int mi = 0; mi < 4; mi++) {
                    float* d = acc[mi][ni];
                    mma8(d[0], d[1], d[2], d[3],
                         ah[mi][0], ah[mi][1], ah[mi][2], ah[mi][3], bh0, bh1);
                    mma8(d[0], d[1], d[2], d[3],
                         ah[mi][0], ah[mi][1], ah[mi][2], ah[mi][3], bl0, bl1);
                    mma8(d[0], d[1], d[2], d[3],
                         al[mi][0], al[mi][1], al[mi][2], al[mi][3], bh0, bh1);
                }
            }
        }
    };

    // ---- pipeline ------------------------------------------------------------
    ldgA(0); ldgB(0);
    sts(0);
    __syncthreads();

    #pragma unroll 1
    for (int i = 0; i < NC; i++) {
        if (i + 1 < NC) { ldgA(i + 1); ldgB(i + 1); }
        compute(i & 1);
        if (i + 1 < NC) sts((i + 1) & 1);
        __syncthreads();
    }

    // ---- epilogue: bias, store, fused BN stats --------------------------------
    float* outp = MODE ? g_y1 : g_y0;
    float* sacc = MODE ? g_s1 : g_s0;
    float* qacc = MODE ? g_q1 : g_q0;

    #pragma unroll
    for (int mi = 0; mi < 4; mi++) {
        const int mrow = m0g + wm * 64 + mi * 16 + (lane >> 2);
        #pragma unroll
        for (int half = 0; half < 2; half++) {
            const int m = mrow + half * 8;
            const float bv = bias[m];
            float* orow = outp + (size_t)m * NTOTv + j0 + wn * 32 + 2 * (lane & 3);
            float s = 0.0f, q = 0.0f;
            #pragma unroll
            for (int ni = 0; ni < 4; ni++) {
                const float v0 = acc[mi][ni][half * 2 + 0] + bv;
                const float v1 = acc[mi][ni][half * 2 + 1] + bv;
                s += v0 + v1;
                q = fmaf(v0, v0, q);
                q = fmaf(v1, v1, q);
                *(float2*)(orow + ni * 8) = make_float2(v0, v1);
            }
            s += __shfl_xor_sync(0xffffffffu, s, 1);
            s += __shfl_xor_sync(0xffffffffu, s, 2);
            q += __shfl_xor_sync(0xffffffffu, q, 1);
            q += __shfl_xor_sync(0xffffffffu, q, 2);
            if ((lane & 3) == 0) {
                atomicAdd(sacc + m, s);
                atomicAdd(qacc + m, q);
            }
        }
    }
}

// ---------------------------------------------------------------------------
// Small kernels
// ---------------------------------------------------------------------------
__global__ void zero_stats()
{
    const int t = threadIdx.x;
    if (t < M0v) { g_s0[t] = 0.0f; g_q0[t] = 0.0f; }
    if (t < M1v) { g_s1[t] = 0.0f; g_q1[t] = 0.0f; }
}

template <bool FIRST>
__global__ void finalize_kernel(const float* __restrict__ g,
                                const float* __restrict__ be, int C)
{
    const int c = blockIdx.x * blockDim.x + threadIdx.x;
    if (c < C) {
        const float* s = FIRST ? g_s0 : g_s1;
        const float* q = FIRST ? g_q0 : g_q1;
        float* scale = FIRST ? g_scale0 : g_scale1;
        float* shift = FIRST ? g_shift0 : g_shift1;
        const float mean = s[c] * (1.0f / NTOTv);
        const float var  = q[c] * (1.0f / NTOTv) - mean * mean;
        const float sc = g[c] * rsqrtf(var + BN_EPS);
        scale[c] = sc;
        shift[c] = be[c] - mean * sc;
    }
}

__global__ __launch_bounds__(256) void bnrelu_out_kernel(float* __restrict__ out)
{
    const int o = blockIdx.x * 256 + threadIdx.x;
    const int n = o & (N1v - 1);
    const int c = (o >> 12) & (M1v - 1);
    const int b = o >> 19;
    const float v = g_y1[(size_t)c * NTOTv + b * N1v + n];
    out[o] = fmaxf(fmaf(v, g_scale1[c], g_shift1[c]), 0.0f);
}

// ---------------------------------------------------------------------------
// Launch
// ---------------------------------------------------------------------------
extern "C" void kernel_launch(void* const* d_in, const int* in_sizes, int n_in,
                              void* d_out, int out_size)
{
    const float* xyz1  = (const float*)d_in[0];
    const float* xyz2  = (const float*)d_in[1];
    const float* feat1 = (const float*)d_in[2];
    const float* feat2 = (const float*)d_in[3];
    const float* w0    = (const float*)d_in[4];
    const float* b0    = (const float*)d_in[5];
    const float* g0    = (const float*)d_in[6];
    const float* be0   = (const float*)d_in[7];
    const float* w1    = (const float*)d_in[8];
    const float* b1    = (const float*)d_in[9];
    const float* g1    = (const float*)d_in[10];
    const float* be1   = (const float*)d_in[11];
    float* out = (float*)d_out;

    constexpr int SMEM_INTERP = 32 * N2v * 4;            // 131072
    constexpr int SMEM_GEMM   = 2 * STAGE_F * 4;         // 143360

    static bool attr_done = false;
    if (!attr_done) {
        cudaFuncSetAttribute(interp_tiled,
            cudaFuncAttributeMaxDynamicSharedMemorySize, SMEM_INTERP);
        cudaFuncSetAttribute(gemm_mma<CINv, 0>,
            cudaFuncAttributeMaxDynamicSharedMemorySize, SMEM_GEMM);
        cudaFuncSetAttribute(gemm_mma<M0v, 1>,
            cudaFuncAttributeMaxDynamicSharedMemorySize, SMEM_GEMM);
        attr_done = true;
    }

    zero_stats<<<1, 256>>>();
    knn_kernel<<<dim3(N1v / 256, NB), 256>>>(xyz1, xyz2);
    interp_tiled<<<NB * 8, 256, SMEM_INTERP>>>(feat2);
    gemm_mma<CINv, 0><<<dim3(M0v / 128, NTOTv / 128), 256, SMEM_GEMM>>>(w0, feat1, b0);
    finalize_kernel<true><<<1, M0v>>>(g0, be0, M0v);
    gemm_mma<M0v, 1><<<dim3(M1v / 128, NTOTv / 128), 256, SMEM_GEMM>>>(w1, nullptr, b1);
    finalize_kernel<false><<<1, M1v>>>(g1, be1, M1v);
    bnrelu_out_kernel<<<(NTOTv * M1v) / 256, 256>>>(out);
}

// round 4
// speedup vs baseline: 1.7697x; 1.2358x over previous
#include <cuda_runtime.h>
#include <cstdint>

// ---------------------------------------------------------------------------
// Problem constants
// ---------------------------------------------------------------------------
constexpr int NB   = 16;
constexpr int N1v  = 4096;
constexpr int N2v  = 1024;
constexpr int C1v  = 128;
constexpr int C2v  = 256;
constexpr int CINv = 384;
constexpr int M0v  = 256;
constexpr int M1v  = 128;
constexpr int NTOTv = NB * N1v;   // 65536
#define BN_EPS 1e-5f

// ---------------------------------------------------------------------------
// Scratch (device globals)
// ---------------------------------------------------------------------------
__device__ float g_interp[(size_t)C2v * NTOTv];   // 64 MB
__device__ float g_y0[(size_t)M0v * NTOTv];       // 64 MB
__device__ float g_y1[(size_t)M1v * NTOTv];       // 32 MB
__device__ int   g_idx3[NTOTv * 3];
__device__ float g_w3[NTOTv * 3];
__device__ float g_s0[M0v], g_q0[M0v], g_scale0[M0v], g_shift0[M0v];
__device__ float g_s1[M1v], g_q1[M1v], g_scale1[M1v], g_shift1[M1v];

// ---------------------------------------------------------------------------
// Helpers: bf16 split-pack and bf16 mma
// ---------------------------------------------------------------------------
// Split two fp32 (x0 at lower k, x1 at upper k) into packed bf16x2 hi and lo:
// x = hi + lo with bf16(hi), bf16(lo); residual ~2^-18 * |x|.
__device__ __forceinline__ void split2(float x0, float x1, uint32_t& h, uint32_t& l) {
    uint32_t hh;
    asm("cvt.rn.bf16x2.f32 %0, %1, %2;" : "=r"(hh) : "f"(x1), "f"(x0));
    const float h0 = __uint_as_float(hh << 16);
    const float h1 = __uint_as_float(hh & 0xFFFF0000u);
    const float l0 = x0 - h0;
    const float l1 = x1 - h1;
    uint32_t ll;
    asm("cvt.rn.bf16x2.f32 %0, %1, %2;" : "=r"(ll) : "f"(l1), "f"(l0));
    h = hh; l = ll;
}

__device__ __forceinline__ void mma16(float* d, const uint32_t* a,
                                      uint32_t b0, uint32_t b1) {
    asm volatile(
        "mma.sync.aligned.m16n8k16.row.col.f32.bf16.bf16.f32 "
        "{%0,%1,%2,%3}, {%4,%5,%6,%7}, {%8,%9}, {%0,%1,%2,%3};"
        : "+f"(d[0]), "+f"(d[1]), "+f"(d[2]), "+f"(d[3])
        : "r"(a[0]), "r"(a[1]), "r"(a[2]), "r"(a[3]), "r"(b0), "r"(b1));
}

// ---------------------------------------------------------------------------
// Kernel: 3-NN (+ stats zeroing folded into block (0,0))
// ---------------------------------------------------------------------------
__global__ __launch_bounds__(256) void knn_kernel(const float* __restrict__ xyz1,
                                                  const float* __restrict__ xyz2)
{
    if (blockIdx.x == 0 && blockIdx.y == 0) {
        const int t = threadIdx.x;
        if (t < M0v) { g_s0[t] = 0.0f; g_q0[t] = 0.0f; }
        if (t < M1v) { g_s1[t] = 0.0f; g_q1[t] = 0.0f; }
    }

    __shared__ float4 s2[N2v];
    const int b = blockIdx.y;
    const float* x2 = xyz2 + (size_t)b * N2v * 3;
    for (int i = threadIdx.x; i < N2v; i += blockDim.x)
        s2[i] = make_float4(x2[i * 3 + 0], x2[i * 3 + 1], x2[i * 3 + 2], 0.0f);
    __syncthreads();

    const int n = blockIdx.x * blockDim.x + threadIdx.x;
    const float* p = xyz1 + ((size_t)b * N1v + n) * 3;
    const float px = p[0], py = p[1], pz = p[2];

    float d0 = 1e30f, d1 = 1e30f, d2 = 1e30f;
    int   i0 = 0,     i1 = 0,     i2 = 0;

    #pragma unroll 4
    for (int i = 0; i < N2v; i++) {
        float4 q = s2[i];
        float dx = px - q.x, dy = py - q.y, dz = pz - q.z;
        float d = dx * dx;
        d = fmaf(dy, dy, d);
        d = fmaf(dz, dz, d);
        if (d < d2) {
            if (d < d1) {
                d2 = d1; i2 = i1;
                if (d < d0) { d1 = d0; i1 = i0; d0 = d; i0 = i; }
                else        { d1 = d;  i1 = i; }
            } else { d2 = d; i2 = i; }
        }
    }

    float w0_ = 1.0f / (d0 + 1e-8f);
    float w1_ = 1.0f / (d1 + 1e-8f);
    float w2_ = 1.0f / (d2 + 1e-8f);
    float inv = 1.0f / (w0_ + w1_ + w2_);

    const int base = ((size_t)b * N1v + n) * 3;
    g_idx3[base + 0] = i0; g_idx3[base + 1] = i1; g_idx3[base + 2] = i2;
    g_w3[base + 0] = w0_ * inv;
    g_w3[base + 1] = w1_ * inv;
    g_w3[base + 2] = w2_ * inv;
}

// ---------------------------------------------------------------------------
// Kernel: SMEM-tiled interpolation
// ---------------------------------------------------------------------------
__global__ __launch_bounds__(256) void interp_tiled(const float* __restrict__ feat2)
{
    extern __shared__ float tile[];  // [32][1024]
    const int b  = blockIdx.x >> 3;
    const int cg = blockIdx.x & 7;
    const float* src = feat2 + ((size_t)b * C2v + cg * 32) * N2v;
    for (int x = threadIdx.x; x < 32 * N2v; x += 256)
        tile[x] = src[x];
    __syncthreads();

    for (int j = threadIdx.x; j < N1v; j += 256) {
        const int jg = b * N1v + j;
        const int i0 = g_idx3[jg * 3 + 0];
        const int i1 = g_idx3[jg * 3 + 1];
        const int i2 = g_idx3[jg * 3 + 2];
        const float w0_ = g_w3[jg * 3 + 0];
        const float w1_ = g_w3[jg * 3 + 1];
        const float w2_ = g_w3[jg * 3 + 2];
        #pragma unroll 8
        for (int c = 0; c < 32; c++) {
            const float* row = tile + c * N2v;
            float v = row[i0] * w0_;
            v = fmaf(row[i1], w1_, v);
            v = fmaf(row[i2], w2_, v);
            g_interp[(size_t)(cg * 32 + c) * NTOTv + jg] = v;
        }
    }
}

// ---------------------------------------------------------------------------
// GEMM via mma.sync bf16 m16n8k16 (3-term split), fused bias + BN-stat atomics.
//   MODE 0: B = concat(feat1, g_interp); out = g_y0, stats -> s0/q0
//   MODE 1: B = relu(bn1(g_y0));         out = g_y1, stats -> s1/q1
// Grid (M/128, NTOT/128); 8 warps (2m x 4n), warp tile 64x32, BK=32.
// SMEM (bf16, stride 34): Ahi[128][34] | Alo | Bhi(j,k)[128][34] | Blo
// ---------------------------------------------------------------------------
constexpr int STRD    = 34;                  // bf16 row stride
constexpr int OFF_ALO = 128 * STRD;          // 4352 (u16 units)
constexpr int OFF_BHI = 2 * 128 * STRD;      // 8704
constexpr int OFF_BLO = 3 * 128 * STRD;      // 13056
constexpr int STAGE_U = 4 * 128 * STRD;      // 17408 u16 = 34816 B

template <int KTOT, int MODE>
__global__ __launch_bounds__(256) void gemm_bf16(const float* __restrict__ Aw,
                                                 const float* __restrict__ feat1,
                                                 const float* __restrict__ bias)
{
    constexpr int NC = KTOT / 32;
    extern __shared__ uint16_t sm[];
    __shared__ float s_scale[M0v], s_shift[M0v];

    const int tid  = threadIdx.x;
    const int lane = tid & 31;
    const int wid  = tid >> 5;
    const int wm   = wid >> 2;
    const int wn   = wid & 3;
    const int m0g  = blockIdx.x * 128;
    const int j0   = blockIdx.y * 128;
    const int b    = j0 >> 12;
    const int n0l  = j0 & (N1v - 1);

    if (MODE == 1) {
        s_scale[tid] = g_scale0[tid];
        s_shift[tid] = g_shift0[tid];
    }
    __syncthreads();

    float acc[4][4][4] = {};
    float4 aR[4], bR[4];

    // ---- register staging loads ------------------------------------------
    auto ldgA = [&](int i) {
        const int k0 = i * 32;
        #pragma unroll
        for (int r = 0; r < 4; r++) {
            const int e  = r * 256 + tid;
            const int m  = e >> 3;
            const int k4 = (e & 7) * 4;
            aR[r] = *(const float4*)(Aw + (size_t)(m0g + m) * KTOT + k0 + k4);
        }
    };
    auto ldgB = [&](int i) {
        const int k0 = i * 32;
        #pragma unroll
        for (int t = 0; t < 2; t++) {
            const int e  = t * 256 + tid;
            const int kp = e >> 5;              // k-pair 0..15
            const int j4 = (e & 31) * 4;
            const int kg = k0 + kp * 2;
            const float *ra, *rb;
            if (MODE == 0) {
                ra = (kg < C1v)
                    ? (feat1 + ((size_t)b * C1v + kg) * N1v + n0l)
                    : (g_interp + (size_t)(kg - C1v) * NTOTv + j0);
                rb = (kg + 1 < C1v)
                    ? (feat1 + ((size_t)b * C1v + kg + 1) * N1v + n0l)
                    : (g_interp + (size_t)(kg + 1 - C1v) * NTOTv + j0);
            } else {
                ra = g_y0 + (size_t)kg * NTOTv + j0;
                rb = g_y0 + (size_t)(kg + 1) * NTOTv + j0;
            }
            float4 va = *(const float4*)(ra + j4);
            float4 vb = *(const float4*)(rb + j4);
            if (MODE == 1) {
                const float sa = s_scale[kg],     ha = s_shift[kg];
                const float sb = s_scale[kg + 1], hb = s_shift[kg + 1];
                va.x = fmaxf(fmaf(va.x, sa, ha), 0.0f);
                va.y = fmaxf(fmaf(va.y, sa, ha), 0.0f);
                va.z = fmaxf(fmaf(va.z, sa, ha), 0.0f);
                va.w = fmaxf(fmaf(va.w, sa, ha), 0.0f);
                vb.x = fmaxf(fmaf(vb.x, sb, hb), 0.0f);
                vb.y = fmaxf(fmaf(vb.y, sb, hb), 0.0f);
                vb.z = fmaxf(fmaf(vb.z, sb, hb), 0.0f);
                vb.w = fmaxf(fmaf(vb.w, sb, hb), 0.0f);
            }
            bR[2 * t]     = va;
            bR[2 * t + 1] = vb;
        }
    };

    // ---- split + store to SMEM --------------------------------------------
    auto sts = [&](int s) {
        uint16_t* S = sm + s * STAGE_U;
        #pragma unroll
        for (int r = 0; r < 4; r++) {
            const int e  = r * 256 + tid;
            const int m  = e >> 3;
            const int k4 = (e & 7) * 4;
            uint32_t h0, l0, h1, l1;
            split2(aR[r].x, aR[r].y, h0, l0);
            split2(aR[r].z, aR[r].w, h1, l1);
            uint16_t* p = S + m * STRD + k4;
            *(uint32_t*)(p)                = h0;
            *(uint32_t*)(p + 2)            = h1;
            *(uint32_t*)(p + OFF_ALO)      = l0;
            *(uint32_t*)(p + OFF_ALO + 2)  = l1;
        }
        #pragma unroll
        for (int t = 0; t < 2; t++) {
            const int e  = t * 256 + tid;
            const int kp = e >> 5;
            const int j4 = (e & 31) * 4;
            const int k  = kp * 2;
            const float4 va = bR[2 * t];
            const float4 vb = bR[2 * t + 1];
            const float ax[4] = {va.x, va.y, va.z, va.w};
            const float bx[4] = {vb.x, vb.y, vb.z, vb.w};
            #pragma unroll
            for (int c = 0; c < 4; c++) {
                uint32_t h, l;
                split2(ax[c], bx[c], h, l);      // (k, k+1) at column j4+c
                uint16_t* p = S + (j4 + c) * STRD + k;
                *(uint32_t*)(p + OFF_BHI) = h;
                *(uint32_t*)(p + OFF_BLO) = l;
            }
        }
    };

    // ---- compute -----------------------------------------------------------
    const int arow = wm * 64 + (lane >> 2);
    const int acol = (lane & 3) * 2;
    const int brow = wn * 32 + (lane >> 2);

    auto compute = [&](int s) {
        const uint16_t* S = sm + s * STAGE_U;
        #pragma unroll
        for (int ks = 0; ks < 2; ks++) {
            const int ko = ks * 16;
            uint32_t ah[4][4], al[4][4];
            #pragma unroll
            for (int mi = 0; mi < 4; mi++) {
                const uint16_t* p = S + (arow + mi * 16) * STRD + acol + ko;
                ah[mi][0] = *(const uint32_t*)(p);
                ah[mi][1] = *(const uint32_t*)(p + 8 * STRD);
                ah[mi][2] = *(const uint32_t*)(p + 8);
                ah[mi][3] = *(const uint32_t*)(p + 8 * STRD + 8);
                al[mi][0] = *(const uint32_t*)(p + OFF_ALO);
                al[mi][1] = *(const uint32_t*)(p + OFF_ALO + 8 * STRD);
                al[mi][2] = *(const uint32_t*)(p + OFF_ALO + 8);
                al[mi][3] = *(const uint32_t*)(p + OFF_ALO + 8 * STRD + 8);
            }
            #pragma unroll
            for (int ni = 0; ni < 4; ni++) {
                const uint16_t* p = S + OFF_BHI + (brow + ni * 8) * STRD + acol + ko;
                const uint32_t bh0 = *(const uint32_t*)(p);
                const uint32_t bh1 = *(const uint32_t*)(p + 8);
                const uint32_t bl0 = *(const uint32_t*)(p + (OFF_BLO - OFF_BHI));
                const uint32_t bl1 = *(const uint32_t*)(p + (OFF_BLO - OFF_BHI) + 8);
                #pragma unroll
                for (int mi = 0; mi < 4; mi++) {
                    mma16(acc[mi][ni], ah[mi], bh0, bh1);
                    mma16(acc[mi][ni], ah[mi], bl0, bl1);
                    mma16(acc[mi][ni], al[mi], bh0, bh1);
                }
            }
        }
    };

    // ---- pipeline ------------------------------------------------------------
    ldgA(0); ldgB(0);
    sts(0);
    __syncthreads();

    #pragma unroll 1
    for (int i = 0; i < NC; i++) {
        if (i + 1 < NC) { ldgA(i + 1); ldgB(i + 1); }
        compute(i & 1);
        if (i + 1 < NC) sts((i + 1) & 1);
        __syncthreads();
    }

    // ---- epilogue: bias, store, fused BN stats --------------------------------
    float* outp = MODE ? g_y1 : g_y0;
    float* sacc = MODE ? g_s1 : g_s0;
    float* qacc = MODE ? g_q1 : g_q0;

    #pragma unroll
    for (int mi = 0; mi < 4; mi++) {
        const int mrow = m0g + wm * 64 + mi * 16 + (lane >> 2);
        #pragma unroll
        for (int half = 0; half < 2; half++) {
            const int m = mrow + half * 8;
            const float bv = bias[m];
            float* orow = outp + (size_t)m * NTOTv + j0 + wn * 32 + 2 * (lane & 3);
            float s = 0.0f, q = 0.0f;
            #pragma unroll
            for (int ni = 0; ni < 4; ni++) {
                const float v0 = acc[mi][ni][half * 2 + 0] + bv;
                const float v1 = acc[mi][ni][half * 2 + 1] + bv;
                s += v0 + v1;
                q = fmaf(v0, v0, q);
                q = fmaf(v1, v1, q);
                *(float2*)(orow + ni * 8) = make_float2(v0, v1);
            }
            s += __shfl_xor_sync(0xffffffffu, s, 1);
            s += __shfl_xor_sync(0xffffffffu, s, 2);
            q += __shfl_xor_sync(0xffffffffu, q, 1);
            q += __shfl_xor_sync(0xffffffffu, q, 2);
            if ((lane & 3) == 0) {
                atomicAdd(sacc + m, s);
                atomicAdd(qacc + m, q);
            }
        }
    }
}

// ---------------------------------------------------------------------------
// Small kernels
// ---------------------------------------------------------------------------
template <bool FIRST>
__global__ void finalize_kernel(const float* __restrict__ g,
                                const float* __restrict__ be, int C)
{
    const int c = blockIdx.x * blockDim.x + threadIdx.x;
    if (c < C) {
        const float* s = FIRST ? g_s0 : g_s1;
        const float* q = FIRST ? g_q0 : g_q1;
        float* scale = FIRST ? g_scale0 : g_scale1;
        float* shift = FIRST ? g_shift0 : g_shift1;
        const float mean = s[c] * (1.0f / NTOTv);
        const float var  = q[c] * (1.0f / NTOTv) - mean * mean;
        const float sc = g[c] * rsqrtf(var + BN_EPS);
        scale[c] = sc;
        shift[c] = be[c] - mean * sc;
    }
}

__global__ __launch_bounds__(256) void bnrelu_out_kernel(float* __restrict__ out)
{
    const int o = (blockIdx.x * 256 + threadIdx.x) * 4;
    const int n = o & (N1v - 1);
    const int c = (o >> 12) & (M1v - 1);
    const int b = o >> 19;
    float4 v = *(const float4*)(g_y1 + (size_t)c * NTOTv + b * N1v + n);
    const float sc = g_scale1[c], sh = g_shift1[c];
    v.x = fmaxf(fmaf(v.x, sc, sh), 0.0f);
    v.y = fmaxf(fmaf(v.y, sc, sh), 0.0f);
    v.z = fmaxf(fmaf(v.z, sc, sh), 0.0f);
    v.w = fmaxf(fmaf(v.w, sc, sh), 0.0f);
    *(float4*)(out + o) = v;
}

// ---------------------------------------------------------------------------
// Launch
// ---------------------------------------------------------------------------
extern "C" void kernel_launch(void* const* d_in, const int* in_sizes, int n_in,
                              void* d_out, int out_size)
{
    const float* xyz1  = (const float*)d_in[0];
    const float* xyz2  = (const float*)d_in[1];
    const float* feat1 = (const float*)d_in[2];
    const float* feat2 = (const float*)d_in[3];
    const float* w0    = (const float*)d_in[4];
    const float* b0    = (const float*)d_in[5];
    const float* g0    = (const float*)d_in[6];
    const float* be0   = (const float*)d_in[7];
    const float* w1    = (const float*)d_in[8];
    const float* b1    = (const float*)d_in[9];
    const float* g1    = (const float*)d_in[10];
    const float* be1   = (const float*)d_in[11];
    float* out = (float*)d_out;

    constexpr int SMEM_INTERP = 32 * N2v * 4;       // 131072
    constexpr int SMEM_GEMM   = 2 * STAGE_U * 2;    // 69632 B

    static bool attr_done = false;
    if (!attr_done) {
        cudaFuncSetAttribute(interp_tiled,
            cudaFuncAttributeMaxDynamicSharedMemorySize, SMEM_INTERP);
        cudaFuncSetAttribute(gemm_bf16<CINv, 0>,
            cudaFuncAttributeMaxDynamicSharedMemorySize, SMEM_GEMM);
        cudaFuncSetAttribute(gemm_bf16<M0v, 1>,
            cudaFuncAttributeMaxDynamicSharedMemorySize, SMEM_GEMM);
        attr_done = true;
    }

    knn_kernel<<<dim3(N1v / 256, NB), 256>>>(xyz1, xyz2);
    interp_tiled<<<NB * 8, 256, SMEM_INTERP>>>(feat2);
    gemm_bf16<CINv, 0><<<dim3(M0v / 128, NTOTv / 128), 256, SMEM_GEMM>>>(w0, feat1, b0);
    finalize_kernel<true><<<1, M0v>>>(g0, be0, M0v);
    gemm_bf16<M0v, 1><<<dim3(M1v / 128, NTOTv / 128), 256, SMEM_GEMM>>>(w1, nullptr, b1);
    finalize_kernel<false><<<1, M1v>>>(g1, be1, M1v);
    bnrelu_out_kernel<<<(NTOTv * M1v) / 1024, 256>>>(out);
}

// round 5
// speedup vs baseline: 1.9627x; 1.1090x over previous
#include <cuda_runtime.h>
#include <cuda_bf16.h>
#include <cstdint>

// ---------------------------------------------------------------------------
// Problem constants
// ---------------------------------------------------------------------------
constexpr int NB   = 16;
constexpr int N1v  = 4096;
constexpr int N2v  = 1024;
constexpr int C1v  = 128;
constexpr int C2v  = 256;
constexpr int CINv = 384;
constexpr int M0v  = 256;
constexpr int M1v  = 128;
constexpr int NTOTv = NB * N1v;   // 65536
#define BN_EPS 1e-5f

// ---------------------------------------------------------------------------
// Scratch (device globals)
// ---------------------------------------------------------------------------
__device__ uint16_t g_Xh[(size_t)CINv * NTOTv];   // 48 MB  X hi (bf16), [k][j]
__device__ uint16_t g_Xl[(size_t)CINv * NTOTv];   // 48 MB  X lo
__device__ uint16_t g_w0h[M0v * CINv], g_w0l[M0v * CINv];
__device__ float g_y0[(size_t)M0v * NTOTv];       // 64 MB
__device__ float g_y1[(size_t)M1v * NTOTv];       // 32 MB
__device__ int   g_idx3[NTOTv * 3];
__device__ float g_w3[NTOTv * 3];
__device__ float g_s0[M0v], g_q0[M0v];
__device__ float g_s1[M1v], g_q1[M1v];

// ---------------------------------------------------------------------------
// Helpers
// ---------------------------------------------------------------------------
__device__ __forceinline__ uint32_t smem_u32(const void* p) {
    uint32_t a;
    asm("{ .reg .u64 t; cvta.to.shared.u64 t, %1; cvt.u32.u64 %0, t; }"
        : "=r"(a) : "l"(p));
    return a;
}

// Split two fp32 into packed bf16x2 hi and lo (x0 in low half, x1 in high half)
__device__ __forceinline__ void split2(float x0, float x1, uint32_t& h, uint32_t& l) {
    uint32_t hh;
    asm("cvt.rn.bf16x2.f32 %0, %1, %2;" : "=r"(hh) : "f"(x1), "f"(x0));
    const float h0 = __uint_as_float(hh << 16);
    const float h1 = __uint_as_float(hh & 0xFFFF0000u);
    const float l0 = x0 - h0;
    const float l1 = x1 - h1;
    uint32_t ll;
    asm("cvt.rn.bf16x2.f32 %0, %1, %2;" : "=r"(ll) : "f"(l1), "f"(l0));
    h = hh; l = ll;
}

__device__ __forceinline__ void split1(float x, uint16_t& h, uint16_t& l) {
    __nv_bfloat16 hb = __float2bfloat16(x);
    const float hf = __bfloat162float(hb);
    __nv_bfloat16 lb = __float2bfloat16(x - hf);
    h = *reinterpret_cast<uint16_t*>(&hb);
    l = *reinterpret_cast<uint16_t*>(&lb);
}

__device__ __forceinline__ void mma16(float* d, const uint32_t* a,
                                      uint32_t b0, uint32_t b1) {
    asm volatile(
        "mma.sync.aligned.m16n8k16.row.col.f32.bf16.bf16.f32 "
        "{%0,%1,%2,%3}, {%4,%5,%6,%7}, {%8,%9}, {%0,%1,%2,%3};"
        : "+f"(d[0]), "+f"(d[1]), "+f"(d[2]), "+f"(d[3])
        : "r"(a[0]), "r"(a[1]), "r"(a[2]), "r"(a[3]), "r"(b0), "r"(b1));
}

__device__ __forceinline__ void ldsm4(uint32_t* r, uint32_t a) {
    asm volatile("ldmatrix.sync.aligned.m8n8.x4.shared.b16 {%0,%1,%2,%3}, [%4];"
        : "=r"(r[0]), "=r"(r[1]), "=r"(r[2]), "=r"(r[3]) : "r"(a));
}
__device__ __forceinline__ void ldsm4t(uint32_t* r, uint32_t a) {
    asm volatile("ldmatrix.sync.aligned.m8n8.x4.trans.shared.b16 {%0,%1,%2,%3}, [%4];"
        : "=r"(r[0]), "=r"(r[1]), "=r"(r[2]), "=r"(r[3]) : "r"(a));
}
__device__ __forceinline__ void cpasync16(uint32_t dst, const void* src) {
    asm volatile("cp.async.cg.shared.global [%0], [%1], 16;" :: "r"(dst), "l"(src));
}
__device__ __forceinline__ void cpcommit() {
    asm volatile("cp.async.commit_group;" ::: "memory");
}

// ---------------------------------------------------------------------------
// prep_misc: zero stats + split w0 into bf16 hi/lo planes
// ---------------------------------------------------------------------------
__global__ __launch_bounds__(256) void prep_misc(const float* __restrict__ w0)
{
    if (blockIdx.x == 0) {
        const int t = threadIdx.x;
        if (t < M0v) { g_s0[t] = 0.0f; g_q0[t] = 0.0f; }
        if (t < M1v) { g_s1[t] = 0.0f; g_q1[t] = 0.0f; }
    }
    const int idx = blockIdx.x * 256 + threadIdx.x;
    if (idx < M0v * CINv) {
        uint16_t h, l;
        split1(w0[idx], h, l);
        g_w0h[idx] = h;
        g_w0l[idx] = l;
    }
}

// ---------------------------------------------------------------------------
// prep_feat1: feat1 fp32 (b,c,n) -> X rows [0,128) bf16 hi/lo, [k][j]
// ---------------------------------------------------------------------------
__global__ __launch_bounds__(256) void prep_feat1(const float* __restrict__ feat1)
{
    const int e = (blockIdx.x * 256 + threadIdx.x) * 4;
    float4 v = *(const float4*)(feat1 + e);
    const int b = e >> 19, c = (e >> 12) & 127, n = e & 4095;
    const size_t dst = (size_t)c * NTOTv + b * N1v + n;
    uint32_t h0, l0, h1, l1;
    split2(v.x, v.y, h0, l0);
    split2(v.z, v.w, h1, l1);
    *(uint32_t*)(g_Xh + dst)     = h0;
    *(uint32_t*)(g_Xh + dst + 2) = h1;
    *(uint32_t*)(g_Xl + dst)     = l0;
    *(uint32_t*)(g_Xl + dst + 2) = l1;
}

// ---------------------------------------------------------------------------
// 3-NN
// ---------------------------------------------------------------------------
__global__ __launch_bounds__(256) void knn_kernel(const float* __restrict__ xyz1,
                                                  const float* __restrict__ xyz2)
{
    __shared__ float4 s2[N2v];
    const int b = blockIdx.y;
    const float* x2 = xyz2 + (size_t)b * N2v * 3;
    for (int i = threadIdx.x; i < N2v; i += blockDim.x)
        s2[i] = make_float4(x2[i * 3 + 0], x2[i * 3 + 1], x2[i * 3 + 2], 0.0f);
    __syncthreads();

    const int n = blockIdx.x * blockDim.x + threadIdx.x;
    const float* p = xyz1 + ((size_t)b * N1v + n) * 3;
    const float px = p[0], py = p[1], pz = p[2];

    float d0 = 1e30f, d1 = 1e30f, d2 = 1e30f;
    int   i0 = 0,     i1 = 0,     i2 = 0;

    #pragma unroll 4
    for (int i = 0; i < N2v; i++) {
        float4 q = s2[i];
        float dx = px - q.x, dy = py - q.y, dz = pz - q.z;
        float d = dx * dx;
        d = fmaf(dy, dy, d);
        d = fmaf(dz, dz, d);
        if (d < d2) {
            if (d < d1) {
                d2 = d1; i2 = i1;
                if (d < d0) { d1 = d0; i1 = i0; d0 = d; i0 = i; }
                else        { d1 = d;  i1 = i; }
            } else { d2 = d; i2 = i; }
        }
    }

    float w0_ = 1.0f / (d0 + 1e-8f);
    float w1_ = 1.0f / (d1 + 1e-8f);
    float w2_ = 1.0f / (d2 + 1e-8f);
    float inv = 1.0f / (w0_ + w1_ + w2_);

    const int base = ((size_t)b * N1v + n) * 3;
    g_idx3[base + 0] = i0; g_idx3[base + 1] = i1; g_idx3[base + 2] = i2;
    g_w3[base + 0] = w0_ * inv;
    g_w3[base + 1] = w1_ * inv;
    g_w3[base + 2] = w2_ * inv;
}

// ---------------------------------------------------------------------------
// Interpolation -> X rows [128, 384) bf16 hi/lo directly
// ---------------------------------------------------------------------------
__global__ __launch_bounds__(256) void interp_tiled(const float* __restrict__ feat2)
{
    extern __shared__ float tile[];  // [32][1024]
    const int b  = blockIdx.x >> 3;
    const int cg = blockIdx.x & 7;
    const float* src = feat2 + ((size_t)b * C2v + cg * 32) * N2v;
    for (int x = threadIdx.x; x < 32 * N2v; x += 256)
        tile[x] = src[x];
    __syncthreads();

    for (int j = threadIdx.x; j < N1v; j += 256) {
        const int jg = b * N1v + j;
        const int i0 = g_idx3[jg * 3 + 0];
        const int i1 = g_idx3[jg * 3 + 1];
        const int i2 = g_idx3[jg * 3 + 2];
        const float w0_ = g_w3[jg * 3 + 0];
        const float w1_ = g_w3[jg * 3 + 1];
        const float w2_ = g_w3[jg * 3 + 2];
        #pragma unroll 8
        for (int c = 0; c < 32; c++) {
            const float* row = tile + c * N2v;
            float v = row[i0] * w0_;
            v = fmaf(row[i1], w1_, v);
            v = fmaf(row[i2], w2_, v);
            uint16_t h, l;
            split1(v, h, l);
            const size_t d = (size_t)(C1v + cg * 32 + c) * NTOTv + jg;
            g_Xh[d] = h;
            g_Xl[d] = l;
        }
    }
}

// ---------------------------------------------------------------------------
// GEMM1: y0 = w0 @ X + b0 (bf16 3-term split), cp.async 3-stage + ldmatrix.
// Grid (2, 512); 8 warps (2m x 4n); warp tile 64x32; BK=32.
// SMEM stage (u16): Ahi[128][40] | Alo | Bhi[32][136] | Blo   (B is [k][j])
// ---------------------------------------------------------------------------
constexpr int G1_SA   = 40;                    // u16
constexpr int G1_SB   = 136;                   // u16
constexpr int G1_ALO  = 128 * G1_SA;           // 5120
constexpr int G1_BHI  = 2 * 128 * G1_SA;       // 10240
constexpr int G1_BLO  = G1_BHI + 32 * G1_SB;   // 14592
constexpr int G1_STG  = G1_BHI + 2 * 32 * G1_SB; // 18944 u16
constexpr int G1_STGB = G1_STG * 2;            // 37888 bytes
constexpr int G1_NC   = CINv / 32;             // 12
constexpr int G1_SMEM = 3 * G1_STGB;           // 113664 bytes

__global__ __launch_bounds__(256) void gemm1(const float* __restrict__ bias)
{
    extern __shared__ uint16_t sm1[];
    const uint32_t smb = smem_u32(sm1);
    const int tid  = threadIdx.x;
    const int lane = tid & 31;
    const int wid  = tid >> 5;
    const int wm   = wid >> 2;
    const int wn   = wid & 3;
    const int m0g  = blockIdx.x * 128;
    const int j0   = blockIdx.y * 128;

    auto issue = [&](int i) {
        const int k0 = i * 32;
        const uint32_t sb = smb + (i % 3) * G1_STGB;
        #pragma unroll
        for (int g = 0; g < 2; g++) {
            const int idx = 2 * tid + g;
            // A granule
            const int m  = idx >> 2, ch = idx & 3;
            const uint16_t* sa = g_w0h + (size_t)(m0g + m) * CINv + k0 + ch * 8;
            const uint16_t* sl = g_w0l + (size_t)(m0g + m) * CINv + k0 + ch * 8;
            const uint32_t da = sb + (m * G1_SA + ch * 8) * 2;
            cpasync16(da, sa);
            cpasync16(da + G1_ALO * 2, sl);
            // B granule
            const int k = idx >> 4, ch2 = idx & 15;
            const uint16_t* sbh = g_Xh + (size_t)(k0 + k) * NTOTv + j0 + ch2 * 8;
            const uint16_t* sbl = g_Xl + (size_t)(k0 + k) * NTOTv + j0 + ch2 * 8;
            const uint32_t db = sb + (G1_BHI + k * G1_SB + ch2 * 8) * 2;
            cpasync16(db, sbh);
            cpasync16(db + (G1_BLO - G1_BHI) * 2, sbl);
        }
        cpcommit();
    };

    // ldmatrix lane-address offsets (bytes within a stage)
    const int q  = lane >> 3;
    const int jj = lane & 7;
    const uint32_t aoff = ((wm * 64 + (q & 1) * 8 + jj) * G1_SA + (q >> 1) * 8) * 2;
    const uint32_t boff = (G1_BHI + ((q & 1) * 8 + jj) * G1_SB
                           + wn * 32 + (q >> 1) * 8) * 2;

    float acc[4][4][4] = {};

    auto compute = [&](int i) {
        const uint32_t sb = smb + (i % 3) * G1_STGB;
        #pragma unroll
        for (int ks = 0; ks < 2; ks++) {
            uint32_t ah[4][4], al[4][4], bh[2][4], bl[2][4];
            #pragma unroll
            for (int mi = 0; mi < 4; mi++) {
                const uint32_t a = sb + aoff + mi * (16 * G1_SA * 2) + ks * 32;
                ldsm4(ah[mi], a);
                ldsm4(al[mi], a + G1_ALO * 2);
            }
            #pragma unroll
            for (int nb = 0; nb < 2; nb++) {
                const uint32_t a = sb + boff + ks * (16 * G1_SB * 2) + nb * 32;
                ldsm4t(bh[nb], a);
                ldsm4t(bl[nb], a + (G1_BLO - G1_BHI) * 2);
            }
            #pragma unroll
            for (int ni = 0; ni < 4; ni++) {
                const uint32_t b0h = bh[ni >> 1][(ni & 1) * 2];
                const uint32_t b1h = bh[ni >> 1][(ni & 1) * 2 + 1];
                const uint32_t b0l = bl[ni >> 1][(ni & 1) * 2];
                const uint32_t b1l = bl[ni >> 1][(ni & 1) * 2 + 1];
                #pragma unroll
                for (int mi = 0; mi < 4; mi++) {
                    mma16(acc[mi][ni], ah[mi], b0h, b1h);
                    mma16(acc[mi][ni], ah[mi], b0l, b1l);
                    mma16(acc[mi][ni], al[mi], b0h, b1h);
                }
            }
        }
    };

    issue(0);
    issue(1);

    #pragma unroll 1
    for (int i = 0; i < G1_NC; i++) {
        if (i < G1_NC - 1) asm volatile("cp.async.wait_group 1;" ::: "memory");
        else               asm volatile("cp.async.wait_group 0;" ::: "memory");
        __syncthreads();
        if (i + 2 < G1_NC) issue(i + 2);
        compute(i);
    }

    // epilogue: bias + store + fused BN stats
    #pragma unroll
    for (int mi = 0; mi < 4; mi++) {
        const int mrow = m0g + wm * 64 + mi * 16 + (lane >> 2);
        #pragma unroll
        for (int half = 0; half < 2; half++) {
            const int m = mrow + half * 8;
            const float bv = bias[m];
            float* orow = g_y0 + (size_t)m * NTOTv + j0 + wn * 32 + 2 * (lane & 3);
            float s = 0.0f, qq = 0.0f;
            #pragma unroll
            for (int ni = 0; ni < 4; ni++) {
                const float v0 = acc[mi][ni][half * 2 + 0] + bv;
                const float v1 = acc[mi][ni][half * 2 + 1] + bv;
                s += v0 + v1;
                qq = fmaf(v0, v0, qq);
                qq = fmaf(v1, v1, qq);
                *(float2*)(orow + ni * 8) = make_float2(v0, v1);
            }
            s  += __shfl_xor_sync(0xffffffffu, s, 1);
            s  += __shfl_xor_sync(0xffffffffu, s, 2);
            qq += __shfl_xor_sync(0xffffffffu, qq, 1);
            qq += __shfl_xor_sync(0xffffffffu, qq, 2);
            if ((lane & 3) == 0) {
                atomicAdd(g_s0 + m, s);
                atomicAdd(g_q0 + m, qq);
            }
        }
    }
}

// ---------------------------------------------------------------------------
// GEMM2: y1 = w1 @ relu(bn1(y0)) + b1; BN1 finalize fused into prologue.
// (round-4 structure: 2-stage reg-staged, split in loader)
// SMEM (u16, stride 34): Ahi[128][34] | Alo | Bhi(j,k)[128][34] | Blo
// ---------------------------------------------------------------------------
constexpr int G2_ST   = 34;
constexpr int G2_ALO  = 128 * G2_ST;
constexpr int G2_BHI  = 2 * 128 * G2_ST;
constexpr int G2_BLO  = 3 * 128 * G2_ST;
constexpr int G2_STG  = 4 * 128 * G2_ST;       // u16
constexpr int G2_SMEM = 2 * G2_STG * 2;        // bytes

__global__ __launch_bounds__(256) void gemm2(const float* __restrict__ Aw,
                                             const float* __restrict__ bias,
                                             const float* __restrict__ g0v,
                                             const float* __restrict__ be0v)
{
    constexpr int KTOT = M0v;
    constexpr int NC = KTOT / 32;
    extern __shared__ uint16_t sm2[];
    __shared__ float s_scale[M0v], s_shift[M0v];

    const int tid  = threadIdx.x;
    const int lane = tid & 31;
    const int wid  = tid >> 5;
    const int wm   = wid >> 2;
    const int wn   = wid & 3;
    const int j0   = blockIdx.x * 128;

    // BN1 finalize (per-CTA, from raw sums)
    {
        const int c = tid;
        const float mean = g_s0[c] * (1.0f / NTOTv);
        const float var  = g_q0[c] * (1.0f / NTOTv) - mean * mean;
        const float sc = g0v[c] * rsqrtf(var + BN_EPS);
        s_scale[c] = sc;
        s_shift[c] = be0v[c] - mean * sc;
    }
    __syncthreads();

    float acc[4][4][4] = {};
    float4 aR[4], bR[4];

    auto ldgA = [&](int i) {
        const int k0 = i * 32;
        #pragma unroll
        for (int r = 0; r < 4; r++) {
            const int e  = r * 256 + tid;
            const int m  = e >> 3;
            const int k4 = (e & 7) * 4;
            aR[r] = *(const float4*)(Aw + (size_t)m * KTOT + k0 + k4);
        }
    };
    auto ldgB = [&](int i) {
        const int k0 = i * 32;
        #pragma unroll
        for (int t = 0; t < 2; t++) {
            const int e  = t * 256 + tid;
            const int kp = e >> 5;
            const int j4 = (e & 31) * 4;
            const int kg = k0 + kp * 2;
            const float* ra = g_y0 + (size_t)kg * NTOTv + j0;
            const float* rb = g_y0 + (size_t)(kg + 1) * NTOTv + j0;
            float4 va = *(const float4*)(ra + j4);
            float4 vb = *(const float4*)(rb + j4);
            const float sa = s_scale[kg],     ha = s_shift[kg];
            const float sb_ = s_scale[kg + 1], hb = s_shift[kg + 1];
            va.x = fmaxf(fmaf(va.x, sa, ha), 0.0f);
            va.y = fmaxf(fmaf(va.y, sa, ha), 0.0f);
            va.z = fmaxf(fmaf(va.z, sa, ha), 0.0f);
            va.w = fmaxf(fmaf(va.w, sa, ha), 0.0f);
            vb.x = fmaxf(fmaf(vb.x, sb_, hb), 0.0f);
            vb.y = fmaxf(fmaf(vb.y, sb_, hb), 0.0f);
            vb.z = fmaxf(fmaf(vb.z, sb_, hb), 0.0f);
            vb.w = fmaxf(fmaf(vb.w, sb_, hb), 0.0f);
            bR[2 * t]     = va;
            bR[2 * t + 1] = vb;
        }
    };
    auto sts = [&](int s) {
        uint16_t* S = sm2 + s * G2_STG;
        #pragma unroll
        for (int r = 0; r < 4; r++) {
            const int e  = r * 256 + tid;
            const int m  = e >> 3;
            const int k4 = (e & 7) * 4;
            uint32_t h0, l0, h1, l1;
            split2(aR[r].x, aR[r].y, h0, l0);
            split2(aR[r].z, aR[r].w, h1, l1);
            uint16_t* p = S + m * G2_ST + k4;
            *(uint32_t*)(p)               = h0;
            *(uint32_t*)(p + 2)           = h1;
            *(uint32_t*)(p + G2_ALO)      = l0;
            *(uint32_t*)(p + G2_ALO + 2)  = l1;
        }
        #pragma unroll
        for (int t = 0; t < 2; t++) {
            const int e  = t * 256 + tid;
            const int kp = e >> 5;
            const int j4 = (e & 31) * 4;
            const int k  = kp * 2;
            const float4 va = bR[2 * t];
            const float4 vb = bR[2 * t + 1];
            const float ax[4] = {va.x, va.y, va.z, va.w};
            const float bx[4] = {vb.x, vb.y, vb.z, vb.w};
            #pragma unroll
            for (int c = 0; c < 4; c++) {
                uint32_t h, l;
                split2(ax[c], bx[c], h, l);
                uint16_t* p = S + (j4 + c) * G2_ST + k;
                *(uint32_t*)(p + G2_BHI) = h;
                *(uint32_t*)(p + G2_BLO) = l;
            }
        }
    };

    const int arow = wm * 64 + (lane >> 2);
    const int acol = (lane & 3) * 2;
    const int brow = wn * 32 + (lane >> 2);

    auto compute = [&](int s) {
        const uint16_t* S = sm2 + s * G2_STG;
        #pragma unroll
        for (int ks = 0; ks < 2; ks++) {
            const int ko = ks * 16;
            uint32_t ah[4][4], al[4][4];
            #pragma unroll
            for (int mi = 0; mi < 4; mi++) {
                const uint16_t* p = S + (arow + mi * 16) * G2_ST + acol + ko;
                ah[mi][0] = *(const uint32_t*)(p);
                ah[mi][1] = *(const uint32_t*)(p + 8 * G2_ST);
                ah[mi][2] = *(const uint32_t*)(p + 8);
                ah[mi][3] = *(const uint32_t*)(p + 8 * G2_ST + 8);
                al[mi][0] = *(const uint32_t*)(p + G2_ALO);
                al[mi][1] = *(const uint32_t*)(p + G2_ALO + 8 * G2_ST);
                al[mi][2] = *(const uint32_t*)(p + G2_ALO + 8);
                al[mi][3] = *(const uint32_t*)(p + G2_ALO + 8 * G2_ST + 8);
            }
            #pragma unroll
            for (int ni = 0; ni < 4; ni++) {
                const uint16_t* p = S + G2_BHI + (brow + ni * 8) * G2_ST + acol + ko;
                const uint32_t bh0 = *(const uint32_t*)(p);
                const uint32_t bh1 = *(const uint32_t*)(p + 8);
                const uint32_t bl0 = *(const uint32_t*)(p + (G2_BLO - G2_BHI));
                const uint32_t bl1 = *(const uint32_t*)(p + (G2_BLO - G2_BHI) + 8);
                #pragma unroll
                for (int mi = 0; mi < 4; mi++) {
                    mma16(acc[mi][ni], ah[mi], bh0, bh1);
                    mma16(acc[mi][ni], ah[mi], bl0, bl1);
                    mma16(acc[mi][ni], al[mi], bh0, bh1);
                }
            }
        }
    };

    ldgA(0); ldgB(0);
    sts(0);
    __syncthreads();

    #pragma unroll 1
    for (int i = 0; i < NC; i++) {
        if (i + 1 < NC) { ldgA(i + 1); ldgB(i + 1); }
        compute(i & 1);
        if (i + 1 < NC) sts((i + 1) & 1);
        __syncthreads();
    }

    #pragma unroll
    for (int mi = 0; mi < 4; mi++) {
        const int mrow = wm * 64 + mi * 16 + (lane >> 2);
        #pragma unroll
        for (int half = 0; half < 2; half++) {
            const int m = mrow + half * 8;
            const float bv = bias[m];
            float* orow = g_y1 + (size_t)m * NTOTv + j0 + wn * 32 + 2 * (lane & 3);
            float s = 0.0f, qq = 0.0f;
            #pragma unroll
            for (int ni = 0; ni < 4; ni++) {
                const float v0 = acc[mi][ni][half * 2 + 0] + bv;
                const float v1 = acc[mi][ni][half * 2 + 1] + bv;
                s += v0 + v1;
                qq = fmaf(v0, v0, qq);
                qq = fmaf(v1, v1, qq);
                *(float2*)(orow + ni * 8) = make_float2(v0, v1);
            }
            s  += __shfl_xor_sync(0xffffffffu, s, 1);
            s  += __shfl_xor_sync(0xffffffffu, s, 2);
            qq += __shfl_xor_sync(0xffffffffu, qq, 1);
            qq += __shfl_xor_sync(0xffffffffu, qq, 2);
            if ((lane & 3) == 0) {
                atomicAdd(g_s1 + m, s);
                atomicAdd(g_q1 + m, qq);
            }
        }
    }
}

// ---------------------------------------------------------------------------
// Final BN2 + ReLU (finalize fused per block; one channel per block)
// ---------------------------------------------------------------------------
__global__ __launch_bounds__(256) void bnrelu_out_kernel(float* __restrict__ out,
                                                         const float* __restrict__ g1v,
                                                         const float* __restrict__ be1v)
{
    __shared__ float ssc, ssh;
    const int ob = blockIdx.x * 1024;
    const int c  = (ob >> 12) & (M1v - 1);
    if (threadIdx.x == 0) {
        const float mean = g_s1[c] * (1.0f / NTOTv);
        const float var  = g_q1[c] * (1.0f / NTOTv) - mean * mean;
        const float sc = g1v[c] * rsqrtf(var + BN_EPS);
        ssc = sc;
        ssh = be1v[c] - mean * sc;
    }
    __syncthreads();

    const int o = ob + threadIdx.x * 4;
    const int n = o & (N1v - 1);
    const int b = o >> 19;
    float4 v = *(const float4*)(g_y1 + (size_t)c * NTOTv + b * N1v + n);
    v.x = fmaxf(fmaf(v.x, ssc, ssh), 0.0f);
    v.y = fmaxf(fmaf(v.y, ssc, ssh), 0.0f);
    v.z = fmaxf(fmaf(v.z, ssc, ssh), 0.0f);
    v.w = fmaxf(fmaf(v.w, ssc, ssh), 0.0f);
    *(float4*)(out + o) = v;
}

// ---------------------------------------------------------------------------
// Launch
// ---------------------------------------------------------------------------
extern "C" void kernel_launch(void* const* d_in, const int* in_sizes, int n_in,
                              void* d_out, int out_size)
{
    const float* xyz1  = (const float*)d_in[0];
    const float* xyz2  = (const float*)d_in[1];
    const float* feat1 = (const float*)d_in[2];
    const float* feat2 = (const float*)d_in[3];
    const float* w0    = (const float*)d_in[4];
    const float* b0    = (const float*)d_in[5];
    const float* g0    = (const float*)d_in[6];
    const float* be0   = (const float*)d_in[7];
    const float* w1    = (const float*)d_in[8];
    const float* b1    = (const float*)d_in[9];
    const float* g1    = (const float*)d_in[10];
    const float* be1   = (const float*)d_in[11];
    float* out = (float*)d_out;

    constexpr int SMEM_INTERP = 32 * N2v * 4;       // 131072

    static bool attr_done = false;
    if (!attr_done) {
        cudaFuncSetAttribute(interp_tiled,
            cudaFuncAttributeMaxDynamicSharedMemorySize, SMEM_INTERP);
        cudaFuncSetAttribute(gemm1,
            cudaFuncAttributeMaxDynamicSharedMemorySize, G1_SMEM);
        cudaFuncSetAttribute(gemm2,
            cudaFuncAttributeMaxDynamicSharedMemorySize, G2_SMEM);
        attr_done = true;
    }

    prep_misc<<<(M0v * CINv + 255) / 256, 256>>>(w0);
    knn_kernel<<<dim3(N1v / 256, NB), 256>>>(xyz1, xyz2);
    prep_feat1<<<(NB * C1v * N1v) / 1024, 256>>>(feat1);
    interp_tiled<<<NB * 8, 256, SMEM_INTERP>>>(feat2);
    gemm1<<<dim3(M0v / 128, NTOTv / 128), 256, G1_SMEM>>>(b0);
    gemm2<<<NTOTv / 128, 256, G2_SMEM>>>(w1, b1, g0, be0);
    bnrelu_out_kernel<<<(NTOTv * M1v) / 1024, 256>>>(out, g1, be1);
}

// round 6
// speedup vs baseline: 2.0273x; 1.0329x over previous
#include <cuda_runtime.h>
#include <cuda_bf16.h>
#include <cstdint>

// ---------------------------------------------------------------------------
// Problem constants
// ---------------------------------------------------------------------------
constexpr int NB   = 16;
constexpr int N1v  = 4096;
constexpr int N2v  = 1024;
constexpr int C1v  = 128;
constexpr int C2v  = 256;
constexpr int CINv = 384;
constexpr int M0v  = 256;
constexpr int M1v  = 128;
constexpr int NTOTv = NB * N1v;   // 65536
#define BN_EPS 1e-5f

// ---------------------------------------------------------------------------
// Scratch (device globals)
// ---------------------------------------------------------------------------
__device__ uint16_t g_Xh[(size_t)CINv * NTOTv];   // 48 MB  X hi (bf16), [k][j]
__device__ uint16_t g_Xl[(size_t)CINv * NTOTv];   // 48 MB  X lo
__device__ uint16_t g_w0h[M0v * CINv], g_w0l[M0v * CINv];
__device__ float g_y0[(size_t)M0v * NTOTv];       // 64 MB
__device__ float g_y1[(size_t)M1v * NTOTv];       // 32 MB
__device__ int   g_idx3[NTOTv * 3];
__device__ float g_w3[NTOTv * 3];
__device__ float g_s0[M0v], g_q0[M0v];
__device__ float g_s1[M1v], g_q1[M1v];

// ---------------------------------------------------------------------------
// Helpers
// ---------------------------------------------------------------------------
__device__ __forceinline__ uint32_t smem_u32(const void* p) {
    uint32_t a;
    asm("{ .reg .u64 t; cvta.to.shared.u64 t, %1; cvt.u32.u64 %0, t; }"
        : "=r"(a) : "l"(p));
    return a;
}

// Split two fp32 into packed bf16x2 hi and lo (x0 in low half, x1 in high half)
__device__ __forceinline__ void split2(float x0, float x1, uint32_t& h, uint32_t& l) {
    uint32_t hh;
    asm("cvt.rn.bf16x2.f32 %0, %1, %2;" : "=r"(hh) : "f"(x1), "f"(x0));
    const float h0 = __uint_as_float(hh << 16);
    const float h1 = __uint_as_float(hh & 0xFFFF0000u);
    const float l0 = x0 - h0;
    const float l1 = x1 - h1;
    uint32_t ll;
    asm("cvt.rn.bf16x2.f32 %0, %1, %2;" : "=r"(ll) : "f"(l1), "f"(l0));
    h = hh; l = ll;
}

__device__ __forceinline__ void split1(float x, uint16_t& h, uint16_t& l) {
    __nv_bfloat16 hb = __float2bfloat16(x);
    const float hf = __bfloat162float(hb);
    __nv_bfloat16 lb = __float2bfloat16(x - hf);
    h = *reinterpret_cast<uint16_t*>(&hb);
    l = *reinterpret_cast<uint16_t*>(&lb);
}

__device__ __forceinline__ void mma16(float* d, const uint32_t* a,
                                      uint32_t b0, uint32_t b1) {
    asm volatile(
        "mma.sync.aligned.m16n8k16.row.col.f32.bf16.bf16.f32 "
        "{%0,%1,%2,%3}, {%4,%5,%6,%7}, {%8,%9}, {%0,%1,%2,%3};"
        : "+f"(d[0]), "+f"(d[1]), "+f"(d[2]), "+f"(d[3])
        : "r"(a[0]), "r"(a[1]), "r"(a[2]), "r"(a[3]), "r"(b0), "r"(b1));
}

__device__ __forceinline__ void ldsm4(uint32_t* r, uint32_t a) {
    asm volatile("ldmatrix.sync.aligned.m8n8.x4.shared.b16 {%0,%1,%2,%3}, [%4];"
        : "=r"(r[0]), "=r"(r[1]), "=r"(r[2]), "=r"(r[3]) : "r"(a));
}
__device__ __forceinline__ void ldsm4t(uint32_t* r, uint32_t a) {
    asm volatile("ldmatrix.sync.aligned.m8n8.x4.trans.shared.b16 {%0,%1,%2,%3}, [%4];"
        : "=r"(r[0]), "=r"(r[1]), "=r"(r[2]), "=r"(r[3]) : "r"(a));
}
__device__ __forceinline__ void cpasync16(uint32_t dst, const void* src) {
    asm volatile("cp.async.cg.shared.global [%0], [%1], 16;" :: "r"(dst), "l"(src));
}
__device__ __forceinline__ void cpcommit() {
    asm volatile("cp.async.commit_group;" ::: "memory");
}

// ---------------------------------------------------------------------------
// prep: zero stats + split w0 into bf16 planes + feat1 -> X rows [0,128)
// grid 8192 x 256
// ---------------------------------------------------------------------------
__global__ __launch_bounds__(256) void prep(const float* __restrict__ w0,
                                            const float* __restrict__ feat1)
{
    const int gidx = blockIdx.x * 256 + threadIdx.x;

    if (blockIdx.x == 0) {
        const int t = threadIdx.x;
        if (t < M0v) { g_s0[t] = 0.0f; g_q0[t] = 0.0f; }
        if (t < M1v) { g_s1[t] = 0.0f; g_q1[t] = 0.0f; }
    }
    if (gidx < M0v * CINv) {
        uint16_t h, l;
        split1(w0[gidx], h, l);
        g_w0h[gidx] = h;
        g_w0l[gidx] = l;
    }

    const int e = gidx * 4;
    float4 v = *(const float4*)(feat1 + e);
    const int b = e >> 19, c = (e >> 12) & 127, n = e & 4095;
    const size_t dst = (size_t)c * NTOTv + b * N1v + n;
    uint32_t h0, l0, h1, l1;
    split2(v.x, v.y, h0, l0);
    split2(v.z, v.w, h1, l1);
    *(uint32_t*)(g_Xh + dst)     = h0;
    *(uint32_t*)(g_Xh + dst + 2) = h1;
    *(uint32_t*)(g_Xl + dst)     = l0;
    *(uint32_t*)(g_Xl + dst + 2) = l1;
}

// ---------------------------------------------------------------------------
// 3-NN
// ---------------------------------------------------------------------------
__global__ __launch_bounds__(256) void knn_kernel(const float* __restrict__ xyz1,
                                                  const float* __restrict__ xyz2)
{
    __shared__ float4 s2[N2v];
    const int b = blockIdx.y;
    const float* x2 = xyz2 + (size_t)b * N2v * 3;
    for (int i = threadIdx.x; i < N2v; i += blockDim.x)
        s2[i] = make_float4(x2[i * 3 + 0], x2[i * 3 + 1], x2[i * 3 + 2], 0.0f);
    __syncthreads();

    const int n = blockIdx.x * blockDim.x + threadIdx.x;
    const float* p = xyz1 + ((size_t)b * N1v + n) * 3;
    const float px = p[0], py = p[1], pz = p[2];

    float d0 = 1e30f, d1 = 1e30f, d2 = 1e30f;
    int   i0 = 0,     i1 = 0,     i2 = 0;

    #pragma unroll 4
    for (int i = 0; i < N2v; i++) {
        float4 q = s2[i];
        float dx = px - q.x, dy = py - q.y, dz = pz - q.z;
        float d = dx * dx;
        d = fmaf(dy, dy, d);
        d = fmaf(dz, dz, d);
        if (d < d2) {
            if (d < d1) {
                d2 = d1; i2 = i1;
                if (d < d0) { d1 = d0; i1 = i0; d0 = d; i0 = i; }
                else        { d1 = d;  i1 = i; }
            } else { d2 = d; i2 = i; }
        }
    }

    float w0_ = 1.0f / (d0 + 1e-8f);
    float w1_ = 1.0f / (d1 + 1e-8f);
    float w2_ = 1.0f / (d2 + 1e-8f);
    float inv = 1.0f / (w0_ + w1_ + w2_);

    const int base = ((size_t)b * N1v + n) * 3;
    g_idx3[base + 0] = i0; g_idx3[base + 1] = i1; g_idx3[base + 2] = i2;
    g_w3[base + 0] = w0_ * inv;
    g_w3[base + 1] = w1_ * inv;
    g_w3[base + 2] = w2_ * inv;
}

// ---------------------------------------------------------------------------
// Interpolation v2: tile transposed [i][c] (stride 36), float4 channel
// gathers, 2 j per thread, packed uint32 stores -> X rows [128, 384)
// ---------------------------------------------------------------------------
constexpr int IT_STR  = 36;
constexpr int IT_SMEM = N2v * IT_STR * 4;   // 147456 bytes

__global__ __launch_bounds__(256) void interp_tiled(const float* __restrict__ feat2)
{
    extern __shared__ float tile[];  // [1024][36]
    const int b  = blockIdx.x >> 3;
    const int cg = blockIdx.x & 7;
    const float* src = feat2 + ((size_t)b * C2v + cg * 32) * N2v;
    for (int x = threadIdx.x; x < 32 * N2v; x += 256) {
        const int c = x >> 10, i = x & 1023;
        tile[i * IT_STR + c] = src[x];
    }
    __syncthreads();

    for (int jb = threadIdx.x * 2; jb < N1v; jb += 512) {
        const int jg = b * N1v + jb;
        const int pa = jg * 3;
        const int ia0 = g_idx3[pa + 0], ia1 = g_idx3[pa + 1], ia2 = g_idx3[pa + 2];
        const int ib0 = g_idx3[pa + 3], ib1 = g_idx3[pa + 4], ib2 = g_idx3[pa + 5];
        const float wa0 = g_w3[pa + 0], wa1 = g_w3[pa + 1], wa2 = g_w3[pa + 2];
        const float wb0 = g_w3[pa + 3], wb1 = g_w3[pa + 4], wb2 = g_w3[pa + 5];
        const float* ta0 = tile + ia0 * IT_STR;
        const float* ta1 = tile + ia1 * IT_STR;
        const float* ta2 = tile + ia2 * IT_STR;
        const float* tb0 = tile + ib0 * IT_STR;
        const float* tb1 = tile + ib1 * IT_STR;
        const float* tb2 = tile + ib2 * IT_STR;

        #pragma unroll
        for (int c4 = 0; c4 < 8; c4++) {
            const float4 A0 = *(const float4*)(ta0 + c4 * 4);
            const float4 A1 = *(const float4*)(ta1 + c4 * 4);
            const float4 A2 = *(const float4*)(ta2 + c4 * 4);
            const float4 B0 = *(const float4*)(tb0 + c4 * 4);
            const float4 B1 = *(const float4*)(tb1 + c4 * 4);
            const float4 B2 = *(const float4*)(tb2 + c4 * 4);
            float va[4], vb[4];
            va[0] = fmaf(wa2, A2.x, fmaf(wa1, A1.x, wa0 * A0.x));
            va[1] = fmaf(wa2, A2.y, fmaf(wa1, A1.y, wa0 * A0.y));
            va[2] = fmaf(wa2, A2.z, fmaf(wa1, A1.z, wa0 * A0.z));
            va[3] = fmaf(wa2, A2.w, fmaf(wa1, A1.w, wa0 * A0.w));
            vb[0] = fmaf(wb2, B2.x, fmaf(wb1, B1.x, wb0 * B0.x));
            vb[1] = fmaf(wb2, B2.y, fmaf(wb1, B1.y, wb0 * B0.y));
            vb[2] = fmaf(wb2, B2.z, fmaf(wb1, B1.z, wb0 * B0.z));
            vb[3] = fmaf(wb2, B2.w, fmaf(wb1, B1.w, wb0 * B0.w));
            #pragma unroll
            for (int q = 0; q < 4; q++) {
                uint32_t h, l;
                split2(va[q], vb[q], h, l);   // (j, j+1) packed
                const size_t d = (size_t)(C1v + cg * 32 + c4 * 4 + q) * NTOTv + jg;
                *(uint32_t*)(g_Xh + d) = h;
                *(uint32_t*)(g_Xl + d) = l;
            }
        }
    }
}

// ---------------------------------------------------------------------------
// GEMM1: y0 = w0 @ X + b0 (bf16 3-term split), cp.async 3-stage + ldmatrix.
// ---------------------------------------------------------------------------
constexpr int G1_SA   = 40;                    // u16
constexpr int G1_SB   = 136;                   // u16
constexpr int G1_ALO  = 128 * G1_SA;           // 5120
constexpr int G1_BHI  = 2 * 128 * G1_SA;       // 10240
constexpr int G1_BLO  = G1_BHI + 32 * G1_SB;   // 14592
constexpr int G1_STG  = G1_BHI + 2 * 32 * G1_SB; // 18944 u16
constexpr int G1_STGB = G1_STG * 2;            // 37888 bytes
constexpr int G1_NC   = CINv / 32;             // 12
constexpr int G1_SMEM = 3 * G1_STGB;           // 113664 bytes

__global__ __launch_bounds__(256) void gemm1(const float* __restrict__ bias)
{
    extern __shared__ uint16_t sm1[];
    const uint32_t smb = smem_u32(sm1);
    const int tid  = threadIdx.x;
    const int lane = tid & 31;
    const int wid  = tid >> 5;
    const int wm   = wid >> 2;
    const int wn   = wid & 3;
    const int m0g  = blockIdx.x * 128;
    const int j0   = blockIdx.y * 128;

    auto issue = [&](int i) {
        const int k0 = i * 32;
        const uint32_t sb = smb + (i % 3) * G1_STGB;
        #pragma unroll
        for (int g = 0; g < 2; g++) {
            const int idx = 2 * tid + g;
            const int m  = idx >> 2, ch = idx & 3;
            const uint16_t* sa = g_w0h + (size_t)(m0g + m) * CINv + k0 + ch * 8;
            const uint16_t* sl = g_w0l + (size_t)(m0g + m) * CINv + k0 + ch * 8;
            const uint32_t da = sb + (m * G1_SA + ch * 8) * 2;
            cpasync16(da, sa);
            cpasync16(da + G1_ALO * 2, sl);
            const int k = idx >> 4, ch2 = idx & 15;
            const uint16_t* sbh = g_Xh + (size_t)(k0 + k) * NTOTv + j0 + ch2 * 8;
            const uint16_t* sbl = g_Xl + (size_t)(k0 + k) * NTOTv + j0 + ch2 * 8;
            const uint32_t db = sb + (G1_BHI + k * G1_SB + ch2 * 8) * 2;
            cpasync16(db, sbh);
            cpasync16(db + (G1_BLO - G1_BHI) * 2, sbl);
        }
        cpcommit();
    };

    const int q  = lane >> 3;
    const int jj = lane & 7;
    const uint32_t aoff = ((wm * 64 + (q & 1) * 8 + jj) * G1_SA + (q >> 1) * 8) * 2;
    const uint32_t boff = (G1_BHI + ((q & 1) * 8 + jj) * G1_SB
                           + wn * 32 + (q >> 1) * 8) * 2;

    float acc[4][4][4] = {};

    auto compute = [&](int i) {
        const uint32_t sb = smb + (i % 3) * G1_STGB;
        #pragma unroll
        for (int ks = 0; ks < 2; ks++) {
            uint32_t ah[4][4], al[4][4], bh[2][4], bl[2][4];
            #pragma unroll
            for (int mi = 0; mi < 4; mi++) {
                const uint32_t a = sb + aoff + mi * (16 * G1_SA * 2) + ks * 32;
                ldsm4(ah[mi], a);
                ldsm4(al[mi], a + G1_ALO * 2);
            }
            #pragma unroll
            for (int nb = 0; nb < 2; nb++) {
                const uint32_t a = sb + boff + ks * (16 * G1_SB * 2) + nb * 32;
                ldsm4t(bh[nb], a);
                ldsm4t(bl[nb], a + (G1_BLO - G1_BHI) * 2);
            }
            #pragma unroll
            for (int ni = 0; ni < 4; ni++) {
                const uint32_t b0h = bh[ni >> 1][(ni & 1) * 2];
                const uint32_t b1h = bh[ni >> 1][(ni & 1) * 2 + 1];
                const uint32_t b0l = bl[ni >> 1][(ni & 1) * 2];
                const uint32_t b1l = bl[ni >> 1][(ni & 1) * 2 + 1];
                #pragma unroll
                for (int mi = 0; mi < 4; mi++) {
                    mma16(acc[mi][ni], ah[mi], b0h, b1h);
                    mma16(acc[mi][ni], ah[mi], b0l, b1l);
                    mma16(acc[mi][ni], al[mi], b0h, b1h);
                }
            }
        }
    };

    issue(0);
    issue(1);

    #pragma unroll 1
    for (int i = 0; i < G1_NC; i++) {
        if (i < G1_NC - 1) asm volatile("cp.async.wait_group 1;" ::: "memory");
        else               asm volatile("cp.async.wait_group 0;" ::: "memory");
        __syncthreads();
        if (i + 2 < G1_NC) issue(i + 2);
        compute(i);
    }

    #pragma unroll
    for (int mi = 0; mi < 4; mi++) {
        const int mrow = m0g + wm * 64 + mi * 16 + (lane >> 2);
        #pragma unroll
        for (int half = 0; half < 2; half++) {
            const int m = mrow + half * 8;
            const float bv = bias[m];
            float* orow = g_y0 + (size_t)m * NTOTv + j0 + wn * 32 + 2 * (lane & 3);
            float s = 0.0f, qq = 0.0f;
            #pragma unroll
            for (int ni = 0; ni < 4; ni++) {
                const float v0 = acc[mi][ni][half * 2 + 0] + bv;
                const float v1 = acc[mi][ni][half * 2 + 1] + bv;
                s += v0 + v1;
                qq = fmaf(v0, v0, qq);
                qq = fmaf(v1, v1, qq);
                *(float2*)(orow + ni * 8) = make_float2(v0, v1);
            }
            s  += __shfl_xor_sync(0xffffffffu, s, 1);
            s  += __shfl_xor_sync(0xffffffffu, s, 2);
            qq += __shfl_xor_sync(0xffffffffu, qq, 1);
            qq += __shfl_xor_sync(0xffffffffu, qq, 2);
            if ((lane & 3) == 0) {
                atomicAdd(g_s0 + m, s);
                atomicAdd(g_q0 + m, qq);
            }
        }
    }
}

// ---------------------------------------------------------------------------
// GEMM2: y1 = w1 @ relu(bn1(y0)) + b1; BN1 finalize fused into prologue.
// ---------------------------------------------------------------------------
constexpr int G2_ST   = 34;
constexpr int G2_ALO  = 128 * G2_ST;
constexpr int G2_BHI  = 2 * 128 * G2_ST;
constexpr int G2_BLO  = 3 * 128 * G2_ST;
constexpr int G2_STG  = 4 * 128 * G2_ST;       // u16
constexpr int G2_SMEM = 2 * G2_STG * 2;        // bytes

__global__ __launch_bounds__(256) void gemm2(const float* __restrict__ Aw,
                                             const float* __restrict__ bias,
                                             const float* __restrict__ g0v,
                                             const float* __restrict__ be0v)
{
    constexpr int KTOT = M0v;
    constexpr int NC = KTOT / 32;
    extern __shared__ uint16_t sm2[];
    __shared__ float s_scale[M0v], s_shift[M0v];

    const int tid  = threadIdx.x;
    const int lane = tid & 31;
    const int wid  = tid >> 5;
    const int wm   = wid >> 2;
    const int wn   = wid & 3;
    const int j0   = blockIdx.x * 128;

    {
        const int c = tid;
        const float mean = g_s0[c] * (1.0f / NTOTv);
        const float var  = g_q0[c] * (1.0f / NTOTv) - mean * mean;
        const float sc = g0v[c] * rsqrtf(var + BN_EPS);
        s_scale[c] = sc;
        s_shift[c] = be0v[c] - mean * sc;
    }
    __syncthreads();

    float acc[4][4][4] = {};
    float4 aR[4], bR[4];

    auto ldgA = [&](int i) {
        const int k0 = i * 32;
        #pragma unroll
        for (int r = 0; r < 4; r++) {
            const int e  = r * 256 + tid;
            const int m  = e >> 3;
            const int k4 = (e & 7) * 4;
            aR[r] = *(const float4*)(Aw + (size_t)m * KTOT + k0 + k4);
        }
    };
    auto ldgB = [&](int i) {
        const int k0 = i * 32;
        #pragma unroll
        for (int t = 0; t < 2; t++) {
            const int e  = t * 256 + tid;
            const int kp = e >> 5;
            const int j4 = (e & 31) * 4;
            const int kg = k0 + kp * 2;
            const float* ra = g_y0 + (size_t)kg * NTOTv + j0;
            const float* rb = g_y0 + (size_t)(kg + 1) * NTOTv + j0;
            float4 va = *(const float4*)(ra + j4);
            float4 vb = *(const float4*)(rb + j4);
            const float sa = s_scale[kg],      ha = s_shift[kg];
            const float sb_ = s_scale[kg + 1], hb = s_shift[kg + 1];
            va.x = fmaxf(fmaf(va.x, sa, ha), 0.0f);
            va.y = fmaxf(fmaf(va.y, sa, ha), 0.0f);
            va.z = fmaxf(fmaf(va.z, sa, ha), 0.0f);
            va.w = fmaxf(fmaf(va.w, sa, ha), 0.0f);
            vb.x = fmaxf(fmaf(vb.x, sb_, hb), 0.0f);
            vb.y = fmaxf(fmaf(vb.y, sb_, hb), 0.0f);
            vb.z = fmaxf(fmaf(vb.z, sb_, hb), 0.0f);
            vb.w = fmaxf(fmaf(vb.w, sb_, hb), 0.0f);
            bR[2 * t]     = va;
            bR[2 * t + 1] = vb;
        }
    };
    auto sts = [&](int s) {
        uint16_t* S = sm2 + s * G2_STG;
        #pragma unroll
        for (int r = 0; r < 4; r++) {
            const int e  = r * 256 + tid;
            const int m  = e >> 3;
            const int k4 = (e & 7) * 4;
            uint32_t h0, l0, h1, l1;
            split2(aR[r].x, aR[r].y, h0, l0);
            split2(aR[r].z, aR[r].w, h1, l1);
            uint16_t* p = S + m * G2_ST + k4;
            *(uint32_t*)(p)               = h0;
            *(uint32_t*)(p + 2)           = h1;
            *(uint32_t*)(p + G2_ALO)      = l0;
            *(uint32_t*)(p + G2_ALO + 2)  = l1;
        }
        #pragma unroll
        for (int t = 0; t < 2; t++) {
            const int e  = t * 256 + tid;
            const int kp = e >> 5;
            const int j4 = (e & 31) * 4;
            const int k  = kp * 2;
            const float4 va = bR[2 * t];
            const float4 vb = bR[2 * t + 1];
            const float ax[4] = {va.x, va.y, va.z, va.w};
            const float bx[4] = {vb.x, vb.y, vb.z, vb.w};
            #pragma unroll
            for (int c = 0; c < 4; c++) {
                uint32_t h, l;
                split2(ax[c], bx[c], h, l);
                uint16_t* p = S + (j4 + c) * G2_ST + k;
                *(uint32_t*)(p + G2_BHI) = h;
                *(uint32_t*)(p + G2_BLO) = l;
            }
        }
    };

    const int arow = wm * 64 + (lane >> 2);
    const int acol = (lane & 3) * 2;
    const int brow = wn * 32 + (lane >> 2);

    auto compute = [&](int s) {
        const uint16_t* S = sm2 + s * G2_STG;
        #pragma unroll
        for (int ks = 0; ks < 2; ks++) {
            const int ko = ks * 16;
            uint32_t ah[4][4], al[4][4];
            #pragma unroll
            for (int mi = 0; mi < 4; mi++) {
                const uint16_t* p = S + (arow + mi * 16) * G2_ST + acol + ko;
                ah[mi][0] = *(const uint32_t*)(p);
                ah[mi][1] = *(const uint32_t*)(p + 8 * G2_ST);
                ah[mi][2] = *(const uint32_t*)(p + 8);
                ah[mi][3] = *(const uint32_t*)(p + 8 * G2_ST + 8);
                al[mi][0] = *(const uint32_t*)(p + G2_ALO);
                al[mi][1] = *(const uint32_t*)(p + G2_ALO + 8 * G2_ST);
                al[mi][2] = *(const uint32_t*)(p + G2_ALO + 8);
                al[mi][3] = *(const uint32_t*)(p + G2_ALO + 8 * G2_ST + 8);
            }
            #pragma unroll
            for (int ni = 0; ni < 4; ni++) {
                const uint16_t* p = S + G2_BHI + (brow + ni * 8) * G2_ST + acol + ko;
                const uint32_t bh0 = *(const uint32_t*)(p);
                const uint32_t bh1 = *(const uint32_t*)(p + 8);
                const uint32_t bl0 = *(const uint32_t*)(p + (G2_BLO - G2_BHI));
                const uint32_t bl1 = *(const uint32_t*)(p + (G2_BLO - G2_BHI) + 8);
                #pragma unroll
                for (int mi = 0; mi < 4; mi++) {
                    mma16(acc[mi][ni], ah[mi], bh0, bh1);
                    mma16(acc[mi][ni], ah[mi], bl0, bl1);
                    mma16(acc[mi][ni], al[mi], bh0, bh1);
                }
            }
        }
    };

    ldgA(0); ldgB(0);
    sts(0);
    __syncthreads();

    #pragma unroll 1
    for (int i = 0; i < NC; i++) {
        if (i + 1 < NC) { ldgA(i + 1); ldgB(i + 1); }
        compute(i & 1);
        if (i + 1 < NC) sts((i + 1) & 1);
        __syncthreads();
    }

    #pragma unroll
    for (int mi = 0; mi < 4; mi++) {
        const int mrow = wm * 64 + mi * 16 + (lane >> 2);
        #pragma unroll
        for (int half = 0; half < 2; half++) {
            const int m = mrow + half * 8;
            const float bv = bias[m];
            float* orow = g_y1 + (size_t)m * NTOTv + j0 + wn * 32 + 2 * (lane & 3);
            float s = 0.0f, qq = 0.0f;
            #pragma unroll
            for (int ni = 0; ni < 4; ni++) {
                const float v0 = acc[mi][ni][half * 2 + 0] + bv;
                const float v1 = acc[mi][ni][half * 2 + 1] + bv;
                s += v0 + v1;
                qq = fmaf(v0, v0, qq);
                qq = fmaf(v1, v1, qq);
                *(float2*)(orow + ni * 8) = make_float2(v0, v1);
            }
            s  += __shfl_xor_sync(0xffffffffu, s, 1);
            s  += __shfl_xor_sync(0xffffffffu, s, 2);
            qq += __shfl_xor_sync(0xffffffffu, qq, 1);
            qq += __shfl_xor_sync(0xffffffffu, qq, 2);
            if ((lane & 3) == 0) {
                atomicAdd(g_s1 + m, s);
                atomicAdd(g_q1 + m, qq);
            }
        }
    }
}

// ---------------------------------------------------------------------------
// Final BN2 + ReLU (finalize fused; one channel per block)
// ---------------------------------------------------------------------------
__global__ __launch_bounds__(256) void bnrelu_out_kernel(float* __restrict__ out,
                                                         const float* __restrict__ g1v,
                                                         const float* __restrict__ be1v)
{
    __shared__ float ssc, ssh;
    const int ob = blockIdx.x * 1024;
    const int c  = (ob >> 12) & (M1v - 1);
    if (threadIdx.x == 0) {
        const float mean = g_s1[c] * (1.0f / NTOTv);
        const float var  = g_q1[c] * (1.0f / NTOTv) - mean * mean;
        const float sc = g1v[c] * rsqrtf(var + BN_EPS);
        ssc = sc;
        ssh = be1v[c] - mean * sc;
    }
    __syncthreads();

    const int o = ob + threadIdx.x * 4;
    const int n = o & (N1v - 1);
    const int b = o >> 19;
    float4 v = *(const float4*)(g_y1 + (size_t)c * NTOTv + b * N1v + n);
    v.x = fmaxf(fmaf(v.x, ssc, ssh), 0.0f);
    v.y = fmaxf(fmaf(v.y, ssc, ssh), 0.0f);
    v.z = fmaxf(fmaf(v.z, ssc, ssh), 0.0f);
    v.w = fmaxf(fmaf(v.w, ssc, ssh), 0.0f);
    *(float4*)(out + o) = v;
}

// ---------------------------------------------------------------------------
// Launch — order matters: gemm1 at slot #4 gets profiled by ncu
// ---------------------------------------------------------------------------
extern "C" void kernel_launch(void* const* d_in, const int* in_sizes, int n_in,
                              void* d_out, int out_size)
{
    const float* xyz1  = (const float*)d_in[0];
    const float* xyz2  = (const float*)d_in[1];
    const float* feat1 = (const float*)d_in[2];
    const float* feat2 = (const float*)d_in[3];
    const float* w0    = (const float*)d_in[4];
    const float* b0    = (const float*)d_in[5];
    const float* g0    = (const float*)d_in[6];
    const float* be0   = (const float*)d_in[7];
    const float* w1    = (const float*)d_in[8];
    const float* b1    = (const float*)d_in[9];
    const float* g1    = (const float*)d_in[10];
    const float* be1   = (const float*)d_in[11];
    float* out = (float*)d_out;

    static bool attr_done = false;
    if (!attr_done) {
        cudaFuncSetAttribute(interp_tiled,
            cudaFuncAttributeMaxDynamicSharedMemorySize, IT_SMEM);
        cudaFuncSetAttribute(gemm1,
            cudaFuncAttributeMaxDynamicSharedMemorySize, G1_SMEM);
        cudaFuncSetAttribute(gemm2,
            cudaFuncAttributeMaxDynamicSharedMemorySize, G2_SMEM);
        attr_done = true;
    }

    prep<<<(NB * C1v * N1v) / 1024, 256>>>(w0, feat1);
    knn_kernel<<<dim3(N1v / 256, NB), 256>>>(xyz1, xyz2);
    interp_tiled<<<NB * 8, 256, IT_SMEM>>>(feat2);
    gemm1<<<dim3(M0v / 128, NTOTv / 128), 256, G1_SMEM>>>(b0);
    gemm2<<<NTOTv / 128, 256, G2_SMEM>>>(w1, b1, g0, be0);
    bnrelu_out_kernel<<<(NTOTv * M1v) / 1024, 256>>>(out, g1, be1);
}